// round 2
// baseline (speedup 1.0000x reference)
#include <cuda_runtime.h>

// ---------------------------------------------------------------------------
// MCA linear attention, fp32. Register-tiled f32x2 GEMM formulation.
//   pass1 : [k;v] = W_kv @ low  (per 128-pixel tile GEMM), softplus(k),
//           block-local reduce attn[pm][c], ksum[pm] -> per-block partials.
//   prep  : reduce partials, sks = ksum+eps, W2[b] = wo . A^T (head-block),
//           store W2 pre-packed for GEMM.
//   pass2 : q = softplus(Wq @ [high;low]); inv = 1/(q . sks) per head;
//           out = W2[b] @ (inv*q) + bo.
// ---------------------------------------------------------------------------

#define DINL __device__ __forceinline__
typedef unsigned long long u64;

namespace mca {

constexpr int Bn   = 8;
constexpr int Np   = 160 * 160;        // 25600
constexpr int TILE = 128;              // pixels per tile
constexpr int TPB  = 256;
constexpr int BLK_PER_B = 18;
constexpr int GRID = Bn * BLK_PER_B;   // 144
constexpr int TILES_PER_B = Np / TILE; // 200
constexpr int XP = 130;                // sX pitch in u64 (per k2 row)
constexpr int KP = 129;                // sK/sV pitch in floats
constexpr float EPSV = 1e-6f;

// no-alloc scratch
__device__ float g_part[GRID * 64 * 8];
__device__ float g_pks [GRID * 64];
__device__ float g_ksum[Bn * 64];        // ksum + eps
__device__ float g_W2  [Bn * 8192];      // pre-packed u64 view [b][k2*64+o]

DINL u64 pk2(float lo, float hi) {
    u64 r; asm("mov.b64 %0, {%1, %2};" : "=l"(r) : "f"(lo), "f"(hi)); return r;
}
DINL void upk2(u64 v, float& lo, float& hi) {
    asm("mov.b64 {%0, %1}, %2;" : "=f"(lo), "=f"(hi) : "l"(v));
}
DINL u64 ffma2(u64 a, u64 b, u64 c) {
    u64 d; asm("fma.rn.f32x2 %0, %1, %2, %3;" : "=l"(d) : "l"(a), "l"(b), "l"(c));
    return d;
}
DINL u64 fmul2(u64 a, u64 b) {
    u64 d; asm("mul.rn.f32x2 %0, %1, %2;" : "=l"(d) : "l"(a), "l"(b));
    return d;
}
DINL float softplus(float x) {
    return fmaxf(x, 0.0f) + log1pf(__expf(-fabsf(x)));
}

// ===========================================================================
// pass1: k/v conv GEMM + attn reduce. grid 144 (b = blk/18), 256 threads.
// dyn smem (u64-first layout):
//   sW   [4096]  u64 : packed [wk;wv], sW[k2*128 + r] = (W[r][2k2], W[r][2k2+1])
//   sX   [4160]  u64 : sX[k2*130 + px]     (aliased by sRed at the end)
//   sK   [8256]  f32 : sK[r*129 + px]   (softplus'd k)
//   sV   [8256]  f32
//   sb   [128]   f32 : [bk(64); bv(64)]
// ===========================================================================
__global__ __launch_bounds__(TPB, 1)
void pass1(const float* __restrict__ low,
           const float* __restrict__ wk, const float* __restrict__ bk,
           const float* __restrict__ wv, const float* __restrict__ bv) {
    extern __shared__ u64 smu[];
    u64*   sW  = smu;
    u64*   sX  = smu + 4096;
    float* sK  = (float*)(smu + 4096 + 4160);
    float* sV  = sK + 8256;
    float* sb  = sV + 8256;
    float* sXf = (float*)sX;
    float* sRed = (float*)sX;   // alias, used after last tile

    const int tid = threadIdx.x;
    const int b   = blockIdx.x / BLK_PER_B;
    const int jb  = blockIdx.x % BLK_PER_B;

    // pack [wk;wv] -> sW (once per block)
    for (int i = tid; i < 4096; i += TPB) {
        int k2 = i >> 7, r = i & 127;
        const float* Wr = (r < 64) ? (wk + r * 64) : (wv + (r - 64) * 64);
        sW[(size_t)k2 * 128 + r] = pk2(Wr[2 * k2], Wr[2 * k2 + 1]);
    }
    if (tid < 64) sb[tid] = bk[tid];
    else if (tid < 128) sb[tid] = bv[tid - 64];

    // GEMM coords: thread tile = 8 oc x 8 px (pixels strided by 16)
    const int ocg = tid >> 4;           // 0..15  -> rows ocg*8..ocg*8+7
    const int pg  = tid & 15;           // pixels pg + 16*j
    const int r0  = ocg * 8;

    // stage-B coords
    const int pm = tid & 63, slice = tid >> 6, p8 = pm & 56;

    float racc[8] = {0, 0, 0, 0, 0, 0, 0, 0};
    float rks = 0.0f;

    for (int t = jb; t < TILES_PER_B; t += BLK_PER_B) {
        const int n0 = t * TILE;
        const float* xb = low + ((size_t)b * 64) * Np + n0;

        __syncthreads();  // weights visible / prev-iter readers done
        // stage X (k2-pair interleaved)
        for (int i = tid; i < 8192; i += TPB) {
            int c = i >> 7, px = i & 127;
            sXf[(c >> 1) * (2 * XP) + px * 2 + (c & 1)] = xb[(size_t)c * Np + px];
        }
        __syncthreads();

        // ---- GEMM: 128 rows x 128 px, f32x2 over k ----
        u64 acc[64];
#pragma unroll
        for (int i = 0; i < 64; i++) acc[i] = 0ull;

#pragma unroll 4
        for (int k2 = 0; k2 < 32; k2++) {
            const ulonglong2* wp = (const ulonglong2*)(sW + (size_t)k2 * 128 + r0);
            ulonglong2 wa = wp[0], wb = wp[1], wc = wp[2], wd = wp[3];
            u64 w2r[8] = {wa.x, wa.y, wb.x, wb.y, wc.x, wc.y, wd.x, wd.y};
            u64 x2r[8];
#pragma unroll
            for (int j = 0; j < 8; j++) x2r[j] = sX[(size_t)k2 * XP + pg + 16 * j];
#pragma unroll
            for (int oi = 0; oi < 8; oi++)
#pragma unroll
                for (int j = 0; j < 8; j++)
                    acc[oi * 8 + j] = ffma2(w2r[oi], x2r[j], acc[oi * 8 + j]);
        }

        // epilogue: hadd + bias, softplus for k rows, store to sK/sV
#pragma unroll
        for (int oi = 0; oi < 8; oi++) {
            const int r = r0 + oi;
            const float bias = sb[r];
#pragma unroll
            for (int j = 0; j < 8; j++) {
                float lo, hi; upk2(acc[oi * 8 + j], lo, hi);
                float val = lo + hi + bias;
                int px = pg + 16 * j;
                if (r < 64) sK[r * KP + px] = softplus(val);
                else        sV[(r - 64) * KP + px] = val;
            }
        }
        __syncthreads();

        // ---- stage B: attn reduce over this tile's 128 pixels ----
        const float* kr = sK + pm * KP + slice * 32;
        const float* vr = sV + p8 * KP + slice * 32;
#pragma unroll 4
        for (int i = 0; i < 32; i++) {
            float kvl = kr[i];
            rks += kvl;
#pragma unroll
            for (int c = 0; c < 8; c++) racc[c] += kvl * vr[c * KP + i];
        }
    }

    // block reduction of 4 slices -> per-block exclusive partials
    __syncthreads();
#pragma unroll
    for (int c = 0; c < 8; c++) sRed[tid * 9 + c] = racc[c];
    sRed[tid * 9 + 8] = rks;
    __syncthreads();
    if (tid < 64) {
        float s[8] = {0, 0, 0, 0, 0, 0, 0, 0};
        float sk = 0.0f;
#pragma unroll
        for (int sl = 0; sl < 4; sl++) {
            const float* p = sRed + (sl * 64 + tid) * 9;
#pragma unroll
            for (int c = 0; c < 8; c++) s[c] += p[c];
            sk += p[8];
        }
#pragma unroll
        for (int c = 0; c < 8; c++) g_part[(blockIdx.x * 64 + tid) * 8 + c] = s[c];
        g_pks[blockIdx.x * 64 + tid] = sk;
    }
}

// ===========================================================================
// prep: reduce partials -> A, sks; W2[b] = wo . A^T (head-block); pre-pack W2.
// grid 8 (one per batch), 512 threads.
// ===========================================================================
__global__ __launch_bounds__(512, 1)
void prep(const float* __restrict__ wo) {
    __shared__ float sA[512];   // [pm][c]
    const int tid = threadIdx.x;
    const int b = blockIdx.x;

    {
        float s = 0.0f;
        for (int j = 0; j < BLK_PER_B; j++)
            s += g_part[((b * BLK_PER_B + j) * 64) * 8 + tid];
        sA[tid] = s;
    }
    if (tid < 64) {
        float s = 0.0f;
        for (int j = 0; j < BLK_PER_B; j++)
            s += g_pks[(b * BLK_PER_B + j) * 64 + tid];
        g_ksum[b * 64 + tid] = s + EPSV;
    }
    __syncthreads();

    // W2[o][pm] = sum_c wo[o][ (pm&56)+c ] * A[pm][c]; store packed:
    // g_W2 float view: [b][ ((pm>>1)*64 + o)*2 + (pm&1) ]
    for (int idx = tid; idx < 4096; idx += 512) {
        int o = idx >> 6, pm = idx & 63;
        int p8 = pm & 56;
        const float* wr = wo + o * 64 + p8;
        const float* ar = sA + pm * 8;
        float acc = 0.0f;
#pragma unroll
        for (int c = 0; c < 8; c++) acc += wr[c] * ar[c];
        g_W2[b * 8192 + ((pm >> 1) * 64 + o) * 2 + (pm & 1)] = acc;
    }
}

// ===========================================================================
// pass2: q GEMMs + per-head rescale + output GEMM. grid 144, 256 threads.
// dyn smem:
//   sWq  [2048] u64 : packed [wqh;wql]
//   sW2  [2048] u64 : packed W2[b]
//   sXh  [4160] u64, sXl [4160] u64, sQ [4160] u64
//   sInv [1024] f32, sks2 [32] u64, sbq [64] f32, sbo [64] f32
// ===========================================================================
__global__ __launch_bounds__(TPB, 1)
void pass2(const float* __restrict__ high, const float* __restrict__ low,
           const float* __restrict__ wqh, const float* __restrict__ bqh,
           const float* __restrict__ wql, const float* __restrict__ bql,
           const float* __restrict__ bo,  float* __restrict__ out) {
    extern __shared__ u64 smu[];
    u64*   sWq  = smu;
    u64*   sW2  = smu + 2048;
    u64*   sXh  = smu + 4096;
    u64*   sXl  = smu + 4096 + 4160;
    u64*   sQ   = smu + 4096 + 2 * 4160;
    float* sInv = (float*)(smu + 4096 + 3 * 4160);
    u64*   sks2 = (u64*)(sInv + 1024);
    float* sbq  = (float*)(sks2 + 32);
    float* sbo  = sbq + 64;
    float* sXhf = (float*)sXh;
    float* sXlf = (float*)sXl;
    float* sQf  = (float*)sQ;

    const int tid = threadIdx.x;
    const int b   = blockIdx.x / BLK_PER_B;
    const int jb  = blockIdx.x % BLK_PER_B;

    // pack q weights; load pre-packed W2[b]; sks pairs; biases
    for (int i = tid; i < 2048; i += TPB) {
        int k2 = i >> 6, r = i & 63;
        const float* Wr = (r < 32) ? (wqh + r * 64) : (wql + (r - 32) * 64);
        sWq[(size_t)k2 * 64 + r] = pk2(Wr[2 * k2], Wr[2 * k2 + 1]);
    }
    {
        const u64* gW2 = (const u64*)g_W2 + (size_t)b * 4096;
        for (int i = tid; i < 4096; i += TPB) sW2[i] = gW2[i];
    }
    if (tid < 32) sks2[tid] = pk2(g_ksum[b * 64 + 2 * tid], g_ksum[b * 64 + 2 * tid + 1]);
    if (tid < 32) sbq[tid] = bqh[tid];
    else if (tid < 64) sbq[tid] = bql[tid - 32];
    if (tid >= 64 && tid < 128) sbo[tid - 64] = bo[tid - 64];

    // GEMM1 coords: half h2 (0=high rows 0..31, 1=low rows 32..63),
    // thread tile 4 rows x 8 px
    const int h2  = tid >> 7;
    const int tt  = tid & 127;
    const int og1 = tt >> 4;            // 0..7
    const int pg  = tt & 15;
    const int r1  = h2 * 32 + og1 * 4;
    // GEMM2 coords: 4 rows x 8 px
    const int og2 = tid >> 4;           // 0..15
    const int r2  = og2 * 4;

    for (int t = jb; t < TILES_PER_B; t += BLK_PER_B) {
        const int n0 = t * TILE;
        const float* xh = high + ((size_t)b * 64) * Np + n0;
        const float* xl = low  + ((size_t)b * 64) * Np + n0;

        __syncthreads();
        for (int i = tid; i < 8192; i += TPB) {
            int c = i >> 7, px = i & 127;
            int o = (c >> 1) * (2 * XP) + px * 2 + (c & 1);
            sXhf[o] = xh[(size_t)c * Np + px];
            sXlf[o] = xl[(size_t)c * Np + px];
        }
        __syncthreads();

        // ---- GEMM1: q (raw) = Wq @ X, softplus -> sQ ----
        {
            const u64* sXin = h2 ? sXl : sXh;
            u64 acc[32];
#pragma unroll
            for (int i = 0; i < 32; i++) acc[i] = 0ull;
#pragma unroll 4
            for (int k2 = 0; k2 < 32; k2++) {
                const ulonglong2* wp = (const ulonglong2*)(sWq + (size_t)k2 * 64 + r1);
                ulonglong2 wa = wp[0], wb = wp[1];
                u64 w2r[4] = {wa.x, wa.y, wb.x, wb.y};
                u64 x2r[8];
#pragma unroll
                for (int j = 0; j < 8; j++) x2r[j] = sXin[(size_t)k2 * XP + pg + 16 * j];
#pragma unroll
                for (int oi = 0; oi < 4; oi++)
#pragma unroll
                    for (int j = 0; j < 8; j++)
                        acc[oi * 8 + j] = ffma2(w2r[oi], x2r[j], acc[oi * 8 + j]);
            }
#pragma unroll
            for (int oi = 0; oi < 4; oi++) {
                const int r = r1 + oi;
                const float bias = sbq[r];
#pragma unroll
                for (int j = 0; j < 8; j++) {
                    float lo, hi; upk2(acc[oi * 8 + j], lo, hi);
                    float q = softplus(lo + hi + bias);
                    int px = pg + 16 * j;
                    sQf[(r >> 1) * (2 * XP) + px * 2 + (r & 1)] = q;
                }
            }
        }
        __syncthreads();

        // ---- per-(head,pixel) inverse norm ----
#pragma unroll
        for (int rr = 0; rr < 4; rr++) {
            int it = tid + TPB * rr;        // 0..1023
            int h = it >> 7, px = it & 127;
            u64 a = 0ull;
#pragma unroll
            for (int a4 = 0; a4 < 4; a4++)
                a = ffma2(sQ[(size_t)(h * 4 + a4) * XP + px], sks2[h * 4 + a4], a);
            float lo, hi; upk2(a, lo, hi);
            sInv[it] = 1.0f / (lo + hi);
        }
        __syncthreads();

        // ---- rescale sQ in place: q' = q * inv[head][px] ----
        for (int i = tid; i < 4096; i += TPB) {
            int k2 = i >> 7, px = i & 127;
            float s = sInv[(k2 >> 2) * 128 + px];
            sQ[(size_t)k2 * XP + px] = fmul2(sQ[(size_t)k2 * XP + px], pk2(s, s));
        }
        __syncthreads();

        // ---- GEMM2: out = W2 @ q' + bo ----
        {
            u64 acc[32];
#pragma unroll
            for (int i = 0; i < 32; i++) acc[i] = 0ull;
#pragma unroll 4
            for (int k2 = 0; k2 < 32; k2++) {
                const ulonglong2* wp = (const ulonglong2*)(sW2 + (size_t)k2 * 64 + r2);
                ulonglong2 wa = wp[0], wb = wp[1];
                u64 w2r[4] = {wa.x, wa.y, wb.x, wb.y};
                u64 x2r[8];
#pragma unroll
                for (int j = 0; j < 8; j++) x2r[j] = sQ[(size_t)k2 * XP + pg + 16 * j];
#pragma unroll
                for (int oi = 0; oi < 4; oi++)
#pragma unroll
                    for (int j = 0; j < 8; j++)
                        acc[oi * 8 + j] = ffma2(w2r[oi], x2r[j], acc[oi * 8 + j]);
            }
            float* ob = out + ((size_t)b * 64) * Np + n0;
#pragma unroll
            for (int oi = 0; oi < 4; oi++) {
                const int r = r2 + oi;
                const float bias = sbo[r];
#pragma unroll
                for (int j = 0; j < 8; j++) {
                    float lo, hi; upk2(acc[oi * 8 + j], lo, hi);
                    int px = pg + 16 * j;
                    ob[(size_t)r * Np + px] = lo + hi + bias;
                }
            }
        }
    }
}

constexpr int SMEM1 = (4096 + 4160) * 8 + (8256 * 2 + 128) * 4;          // 132608
constexpr int SMEM2 = (4096 + 3 * 4160) * 8 + (1024 + 64 + 64) * 4 + 32 * 8; // 137472

}  // namespace mca

// ---------------------------------------------------------------------------
extern "C" void kernel_launch(void* const* d_in, const int* in_sizes, int n_in,
                              void* d_out, int out_size) {
    using namespace mca;
    (void)in_sizes; (void)n_in; (void)out_size;

    const float* high = (const float*)d_in[0];
    const float* low  = (const float*)d_in[1];
    const float* wqh  = (const float*)d_in[2];
    const float* bqh  = (const float*)d_in[3];
    const float* wql  = (const float*)d_in[4];
    const float* bql  = (const float*)d_in[5];
    const float* wk   = (const float*)d_in[6];
    const float* bk   = (const float*)d_in[7];
    const float* wv   = (const float*)d_in[8];
    const float* bv   = (const float*)d_in[9];
    const float* wo   = (const float*)d_in[10];
    const float* bo   = (const float*)d_in[11];
    float* out = (float*)d_out;

    cudaFuncSetAttribute(pass1, cudaFuncAttributeMaxDynamicSharedMemorySize, SMEM1);
    cudaFuncSetAttribute(pass2, cudaFuncAttributeMaxDynamicSharedMemorySize, SMEM2);

    pass1<<<GRID, TPB, SMEM1>>>(low, wk, bk, wv, bv);
    prep<<<Bn, 512>>>(wo);
    pass2<<<GRID, TPB, SMEM2>>>(high, low, wqh, bqh, wql, bql, bo, out);
}

// round 6
// speedup vs baseline: 1.4625x; 1.4625x over previous
#include <cuda_runtime.h>

// ---------------------------------------------------------------------------
// MCA linear attention, fp32, FFMA2 register-tiled GEMMs, 512-thread blocks.
//   zero  : clear atomic accumulators
//   pass1 : [k;v] = Wkv @ low per 128-px tile; softplus(k); block-local
//           attn/ksum reduce; smem-reduced atomic flush per batch segment.
//   prep  : sks = ksum+eps; W2[b] = wo . A^T (head-block), packed for GEMM.
//   pass2 : q = softplus(Wq @ [high;low]); inv = 1/(q . sks); out = W2 @ (inv*q) + bo.
// ---------------------------------------------------------------------------

#define DINL __device__ __forceinline__
typedef unsigned long long u64;

namespace mca {

constexpr int Bn = 8;
constexpr int Np = 25600;
constexpr int TILE = 128;
constexpr int TPB = 512;
constexpr int GRID = 148;
constexpr int TILES_TOTAL = 1600;   // Bn*Np/TILE
constexpr int TPBATCH = 200;        // tiles per batch
constexpr int XP = 130;             // u64 pitch for packed activations
constexpr int KP = 132;             // f32 pitch for k/v staging (mult of 4)
constexpr float EPSV = 1e-6f;

__device__ float g_attn[Bn * 64 * 8];   // [b][pm][c]  (atomic accum)
__device__ float g_ksum_raw[Bn * 64];
__device__ float g_ksum[Bn * 64];       // +eps
__device__ float g_W2[Bn * 4096];       // dense packed; u64 view: [b*2048 + k2*64 + o]

DINL u64 pk2(float lo, float hi) {
    u64 r; asm("mov.b64 %0, {%1, %2};" : "=l"(r) : "f"(lo), "f"(hi)); return r;
}
DINL void upk2(u64 v, float& lo, float& hi) {
    asm("mov.b64 {%0, %1}, %2;" : "=f"(lo), "=f"(hi) : "l"(v));
}
DINL u64 ffma2(u64 a, u64 b, u64 c) {
    u64 d; asm("fma.rn.f32x2 %0, %1, %2, %3;" : "=l"(d) : "l"(a), "l"(b), "l"(c));
    return d;
}
DINL u64 fmul2(u64 a, u64 b) {
    u64 d; asm("mul.rn.f32x2 %0, %1, %2;" : "=l"(d) : "l"(a), "l"(b));
    return d;
}
DINL float softplus(float x) {
    return fmaxf(x, 0.0f) + log1pf(__expf(-fabsf(x)));
}

// ---------------------------------------------------------------------------
__global__ void zero_scratch() {
    int i = blockIdx.x * blockDim.x + threadIdx.x;
    int stride = gridDim.x * blockDim.x;
    for (int j = i; j < Bn * 64 * 8; j += stride) g_attn[j] = 0.0f;
    for (int j = i; j < Bn * 64; j += stride) g_ksum_raw[j] = 0.0f;
}

// ---------------------------------------------------------------------------
// pass1 smem (u64-first):
//   sW [4096] u64, sX [4160] u64 (aliased by sRed for flush),
//   sKV [128*132] f32, sb [128] f32
// ---------------------------------------------------------------------------
__global__ __launch_bounds__(TPB, 1)
void pass1(const float* __restrict__ low,
           const float* __restrict__ wk, const float* __restrict__ bk,
           const float* __restrict__ wv, const float* __restrict__ bv) {
    extern __shared__ u64 smu[];
    u64*   sW  = smu;                      // 4096
    u64*   sX  = smu + 4096;               // 4160
    float* sKV = (float*)(smu + 8256);     // 128*KP
    float* sb  = sKV + 128 * KP;           // 128
    float* sRed = (float*)sX;              // alias (flush only)

    const int tid = threadIdx.x;
    const int blk = blockIdx.x;
    const int t0 = (blk * TILES_TOTAL) / GRID;
    const int t1 = ((blk + 1) * TILES_TOTAL) / GRID;

    for (int i = tid; i < 4096; i += TPB) {
        int k2 = i >> 7, r = i & 127;
        const float* Wr = (r < 64) ? (wk + r * 64) : (wv + (r - 64) * 64);
        sW[k2 * 128 + r] = pk2(Wr[2 * k2], Wr[2 * k2 + 1]);
    }
    if (tid < 64) sb[tid] = bk[tid];
    else if (tid < 128) sb[tid] = bv[tid - 64];

    // GEMM tile: 8 oc rows x 4 px per thread
    const int ocg = tid >> 5;          // 0..15
    const int r0  = ocg * 8;
    const int pgq = tid & 31;          // px = 2*pgq + {0,1} + 64*jj
    const bool isK = (r0 < 64);

    // stage-B identity
    const int pm = tid & 63, slice = tid >> 6, p8 = pm & 56;
    float racc[8] = {0, 0, 0, 0, 0, 0, 0, 0};
    float rks = 0.0f;
    int bprev = t0 / TPBATCH;

#define P1_FLUSH(BIDX)                                                        \
    do {                                                                      \
        __syncthreads();                                                      \
        _Pragma("unroll")                                                     \
        for (int c = 0; c < 8; c++) sRed[tid * 9 + c] = racc[c];              \
        sRed[tid * 9 + 8] = rks;                                              \
        __syncthreads();                                                      \
        if (tid < 64) {                                                       \
            float s[9] = {0, 0, 0, 0, 0, 0, 0, 0, 0};                         \
            _Pragma("unroll")                                                 \
            for (int sl = 0; sl < 8; sl++) {                                  \
                const float* p = sRed + (sl * 64 + tid) * 9;                  \
                _Pragma("unroll")                                             \
                for (int c = 0; c < 9; c++) s[c] += p[c];                     \
            }                                                                 \
            _Pragma("unroll")                                                 \
            for (int c = 0; c < 8; c++)                                       \
                atomicAdd(g_attn + ((BIDX) * 64 + tid) * 8 + c, s[c]);        \
            atomicAdd(g_ksum_raw + (BIDX) * 64 + tid, s[8]);                  \
        }                                                                     \
        _Pragma("unroll")                                                     \
        for (int c = 0; c < 8; c++) racc[c] = 0.0f;                           \
        rks = 0.0f;                                                           \
    } while (0)

    for (int t = t0; t < t1; ++t) {
        const int b = t / TPBATCH;
        if (b != bprev) { P1_FLUSH(bprev); bprev = b; }
        const int n0 = (t % TPBATCH) * TILE;
        const float* xb = low + ((size_t)b * 64) * Np + n0;

        __syncthreads();   // prior sX/sKV readers done
        for (int i = tid; i < 4096; i += TPB) {
            int k2 = i >> 7, px = i & 127;
            sX[k2 * XP + px] =
                pk2(xb[(size_t)(2 * k2) * Np + px], xb[(size_t)(2 * k2 + 1) * Np + px]);
        }
        __syncthreads();

        // ---- GEMM: 128 rows x 128 px over 32 k2 ----
        u64 acc[32];
#pragma unroll
        for (int i = 0; i < 32; i++) acc[i] = 0ull;
#pragma unroll 4
        for (int k2 = 0; k2 < 32; k2++) {
            const ulonglong2* wp = (const ulonglong2*)(sW + k2 * 128 + r0);
            ulonglong2 w01 = wp[0], w23 = wp[1], w45 = wp[2], w67 = wp[3];
            u64 w2r[8] = {w01.x, w01.y, w23.x, w23.y, w45.x, w45.y, w67.x, w67.y};
            ulonglong2 xa = *(const ulonglong2*)(sX + k2 * XP + 2 * pgq);
            ulonglong2 xc = *(const ulonglong2*)(sX + k2 * XP + 64 + 2 * pgq);
            u64 x2r[4] = {xa.x, xa.y, xc.x, xc.y};
#pragma unroll
            for (int oi = 0; oi < 8; oi++)
#pragma unroll
                for (int j = 0; j < 4; j++)
                    acc[oi * 4 + j] = ffma2(w2r[oi], x2r[j], acc[oi * 4 + j]);
        }

        // epilogue -> sKV (paired STS.64)
#pragma unroll
        for (int oi = 0; oi < 8; oi++) {
            const int r = r0 + oi;
            const float bias = sb[r];
#pragma unroll
            for (int jj = 0; jj < 2; jj++) {
                float lo0, hi0, lo1, hi1;
                upk2(acc[oi * 4 + 2 * jj], lo0, hi0);
                upk2(acc[oi * 4 + 2 * jj + 1], lo1, hi1);
                float v0 = lo0 + hi0 + bias;
                float v1 = lo1 + hi1 + bias;
                if (isK) { v0 = softplus(v0); v1 = softplus(v1); }
                *(u64*)(sKV + r * KP + 2 * pgq + 64 * jj) = pk2(v0, v1);
            }
        }
        __syncthreads();

        // ---- stage B: attn reduce (float4 reads) ----
        const float* kr = sKV + pm * KP + slice * 16;
        const float* vr = sKV + (64 + p8) * KP + slice * 16;
#pragma unroll
        for (int ii = 0; ii < 4; ii++) {
            float4 kq = *(const float4*)(kr + 4 * ii);
            rks += (kq.x + kq.y) + (kq.z + kq.w);
#pragma unroll
            for (int c = 0; c < 8; c++) {
                float4 vq = *(const float4*)(vr + c * KP + 4 * ii);
                racc[c] += kq.x * vq.x + kq.y * vq.y + kq.z * vq.z + kq.w * vq.w;
            }
        }
    }
    P1_FLUSH(bprev);
#undef P1_FLUSH
}

// ---------------------------------------------------------------------------
__global__ __launch_bounds__(512, 1)
void prep(const float* __restrict__ wo) {
    __shared__ float sA[512];
    const int tid = threadIdx.x;
    const int b = blockIdx.x;
    sA[tid] = g_attn[b * 512 + tid];
    if (tid < 64) g_ksum[b * 64 + tid] = g_ksum_raw[b * 64 + tid] + EPSV;
    __syncthreads();
    // dense pack: float offset b*4096 + ((pm>>1)*64 + o)*2 + (pm&1)
    for (int idx = tid; idx < 4096; idx += 512) {
        int o = idx >> 6, pm = idx & 63;
        const float* wr = wo + o * 64 + (pm & 56);
        const float* ar = sA + pm * 8;
        float acc = 0.0f;
#pragma unroll
        for (int c = 0; c < 8; c++) acc += wr[c] * ar[c];
        g_W2[b * 4096 + ((pm >> 1) * 64 + o) * 2 + (pm & 1)] = acc;
    }
}

// ---------------------------------------------------------------------------
// pass2 smem: sWq[2048] sW2[2048] sXh[4160] sXl[4160] sQ[4160] u64,
//             sInv[1024] f32, sks2[32] u64, sbq[64], sbo[64]
// ---------------------------------------------------------------------------
__global__ __launch_bounds__(TPB, 1)
void pass2(const float* __restrict__ high, const float* __restrict__ low,
           const float* __restrict__ wqh, const float* __restrict__ bqh,
           const float* __restrict__ wql, const float* __restrict__ bql,
           const float* __restrict__ bo, float* __restrict__ out) {
    extern __shared__ u64 smu[];
    u64*   sWq  = smu;                         // 2048
    u64*   sW2  = smu + 2048;                  // 2048
    u64*   sXh  = smu + 4096;                  // 4160
    u64*   sXl  = smu + 4096 + 4160;           // 4160
    u64*   sQ   = smu + 4096 + 2 * 4160;       // 4160
    float* sInv = (float*)(smu + 4096 + 3 * 4160);
    u64*   sks2 = (u64*)(sInv + 1024);
    float* sbq  = (float*)(sks2 + 32);
    float* sbo  = sbq + 64;

    const int tid = threadIdx.x;
    const int blk = blockIdx.x;
    const int t0 = (blk * TILES_TOTAL) / GRID;
    const int t1 = ((blk + 1) * TILES_TOTAL) / GRID;

    for (int i = tid; i < 2048; i += TPB) {
        int k2 = i >> 6, r = i & 63;
        const float* Wr = (r < 32) ? (wqh + r * 64) : (wql + (r - 32) * 64);
        sWq[k2 * 64 + r] = pk2(Wr[2 * k2], Wr[2 * k2 + 1]);
    }
    if (tid < 32) sbq[tid] = bqh[tid];
    else if (tid < 64) sbq[tid] = bql[tid - 32];
    else if (tid < 128) sbo[tid - 64] = bo[tid - 64];

    // GEMM1: 8 rows x 2 px; halves on different inputs
    const int half = tid >> 8;
    const int t8   = tid & 255;
    const int ocg1 = t8 >> 6;                // 0..3
    const int r1   = half * 32 + ocg1 * 8;
    const int pg1  = t8 & 63;                // px pair 2*pg1
    // GEMM2: 8 rows x 2 px
    const int ocg2 = tid >> 6;               // 0..7
    const int r2   = ocg2 * 8;
    const int pg2  = tid & 63;

    int bprev = -1;

    for (int t = t0; t < t1; ++t) {
        const int b = t / TPBATCH;
        if (b != bprev) {
            __syncthreads();   // prior GEMM2 reads of sW2 / norm reads of sks2 done
            const u64* gW2 = (const u64*)g_W2 + (size_t)b * 2048;
            for (int i = tid; i < 2048; i += TPB) sW2[i] = gW2[i];
            if (tid < 32)
                sks2[tid] = pk2(g_ksum[b * 64 + 2 * tid], g_ksum[b * 64 + 2 * tid + 1]);
            bprev = b;
        }
        const int n0 = (t % TPBATCH) * TILE;
        const float* xh = high + ((size_t)b * 64) * Np + n0;
        const float* xl = low  + ((size_t)b * 64) * Np + n0;

        __syncthreads();
        for (int i = tid; i < 4096; i += TPB) {
            int k2 = i >> 7, px = i & 127;
            sXh[k2 * XP + px] =
                pk2(xh[(size_t)(2 * k2) * Np + px], xh[(size_t)(2 * k2 + 1) * Np + px]);
            sXl[k2 * XP + px] =
                pk2(xl[(size_t)(2 * k2) * Np + px], xl[(size_t)(2 * k2 + 1) * Np + px]);
        }
        __syncthreads();

        // ---- GEMM1: q = softplus(Wq @ X) -> sQ packed ----
        {
            const u64* sXin = half ? sXl : sXh;
            u64 acc[16];
#pragma unroll
            for (int i = 0; i < 16; i++) acc[i] = 0ull;
#pragma unroll 4
            for (int k2 = 0; k2 < 32; k2++) {
                const ulonglong2* wp = (const ulonglong2*)(sWq + k2 * 64 + r1);
                ulonglong2 w01 = wp[0], w23 = wp[1], w45 = wp[2], w67 = wp[3];
                u64 w2r[8] = {w01.x, w01.y, w23.x, w23.y, w45.x, w45.y, w67.x, w67.y};
                ulonglong2 xa = *(const ulonglong2*)(sXin + k2 * XP + 2 * pg1);
#pragma unroll
                for (int oi = 0; oi < 8; oi++) {
                    acc[oi * 2 + 0] = ffma2(w2r[oi], xa.x, acc[oi * 2 + 0]);
                    acc[oi * 2 + 1] = ffma2(w2r[oi], xa.y, acc[oi * 2 + 1]);
                }
            }
#pragma unroll
            for (int oi2 = 0; oi2 < 4; oi2++) {
                const int ra = r1 + 2 * oi2;
                const float ba0 = sbq[ra], ba1 = sbq[ra + 1];
                float lo, hi;
                upk2(acc[(2 * oi2) * 2 + 0], lo, hi);     float v00 = softplus(lo + hi + ba0);
                upk2(acc[(2 * oi2) * 2 + 1], lo, hi);     float v01 = softplus(lo + hi + ba0);
                upk2(acc[(2 * oi2 + 1) * 2 + 0], lo, hi); float v10 = softplus(lo + hi + ba1);
                upk2(acc[(2 * oi2 + 1) * 2 + 1], lo, hi); float v11 = softplus(lo + hi + ba1);
                ulonglong2 st;
                st.x = pk2(v00, v10);
                st.y = pk2(v01, v11);
                *(ulonglong2*)(sQ + (ra >> 1) * XP + 2 * pg1) = st;
            }
        }
        __syncthreads();

        // ---- fused norm + rescale: each (h,px) unit owns its 4 sQ words ----
#pragma unroll
        for (int rr = 0; rr < 2; rr++) {
            int it = tid + 512 * rr;
            int h = it >> 7, px = it & 127;
            u64 q0 = sQ[(h * 4 + 0) * XP + px];
            u64 q1 = sQ[(h * 4 + 1) * XP + px];
            u64 q2 = sQ[(h * 4 + 2) * XP + px];
            u64 q3 = sQ[(h * 4 + 3) * XP + px];
            u64 a = ffma2(q0, sks2[h * 4 + 0], 0ull);
            a = ffma2(q1, sks2[h * 4 + 1], a);
            a = ffma2(q2, sks2[h * 4 + 2], a);
            a = ffma2(q3, sks2[h * 4 + 3], a);
            float lo, hi; upk2(a, lo, hi);
            float inv = 1.0f / (lo + hi);
            u64 iv = pk2(inv, inv);
            sQ[(h * 4 + 0) * XP + px] = fmul2(q0, iv);
            sQ[(h * 4 + 1) * XP + px] = fmul2(q1, iv);
            sQ[(h * 4 + 2) * XP + px] = fmul2(q2, iv);
            sQ[(h * 4 + 3) * XP + px] = fmul2(q3, iv);
        }
        __syncthreads();

        // ---- GEMM2: out = W2 @ q' + bo ----
        {
            u64 acc[16];
#pragma unroll
            for (int i = 0; i < 16; i++) acc[i] = 0ull;
#pragma unroll 4
            for (int k2 = 0; k2 < 32; k2++) {
                const ulonglong2* wp = (const ulonglong2*)(sW2 + k2 * 64 + r2);
                ulonglong2 w01 = wp[0], w23 = wp[1], w45 = wp[2], w67 = wp[3];
                u64 w2r[8] = {w01.x, w01.y, w23.x, w23.y, w45.x, w45.y, w67.x, w67.y};
                ulonglong2 xa = *(const ulonglong2*)(sQ + k2 * XP + 2 * pg2);
#pragma unroll
                for (int oi = 0; oi < 8; oi++) {
                    acc[oi * 2 + 0] = ffma2(w2r[oi], xa.x, acc[oi * 2 + 0]);
                    acc[oi * 2 + 1] = ffma2(w2r[oi], xa.y, acc[oi * 2 + 1]);
                }
            }
            float* ob = out + ((size_t)b * 64) * Np + n0;
#pragma unroll
            for (int oi = 0; oi < 8; oi++) {
                const int r = r2 + oi;
                const float bias = sbo[r];
                float lo0, hi0, lo1, hi1;
                upk2(acc[oi * 2 + 0], lo0, hi0);
                upk2(acc[oi * 2 + 1], lo1, hi1);
                *(float2*)(ob + (size_t)r * Np + 2 * pg2) =
                    make_float2(lo0 + hi0 + bias, lo1 + hi1 + bias);
            }
        }
    }
}

constexpr int SMEM1 = 8256 * 8 + 128 * KP * 4 + 128 * 4;  // 134,144
constexpr int SMEM2 = (4096 + 3 * 4160) * 8 + 1024 * 4 + 32 * 8 + 128 * 4;  // 137,472

}  // namespace mca

// ---------------------------------------------------------------------------
extern "C" void kernel_launch(void* const* d_in, const int* in_sizes, int n_in,
                              void* d_out, int out_size) {
    using namespace mca;
    (void)in_sizes; (void)n_in; (void)out_size;

    const float* high = (const float*)d_in[0];
    const float* low  = (const float*)d_in[1];
    const float* wqh  = (const float*)d_in[2];
    const float* bqh  = (const float*)d_in[3];
    const float* wql  = (const float*)d_in[4];
    const float* bql  = (const float*)d_in[5];
    const float* wk   = (const float*)d_in[6];
    const float* bk   = (const float*)d_in[7];
    const float* wv   = (const float*)d_in[8];
    const float* bv   = (const float*)d_in[9];
    const float* wo   = (const float*)d_in[10];
    const float* bo   = (const float*)d_in[11];
    float* out = (float*)d_out;

    cudaFuncSetAttribute(pass1, cudaFuncAttributeMaxDynamicSharedMemorySize, SMEM1);
    cudaFuncSetAttribute(pass2, cudaFuncAttributeMaxDynamicSharedMemorySize, SMEM2);

    zero_scratch<<<8, 512>>>();
    pass1<<<GRID, TPB, SMEM1>>>(low, wk, bk, wv, bv);
    prep<<<Bn, 512>>>(wo);
    pass2<<<GRID, TPB, SMEM2>>>(high, low, wqh, bqh, wql, bql, bo, out);
}

// round 7
// speedup vs baseline: 1.5823x; 1.0819x over previous
#include <cuda_runtime.h>

// ---------------------------------------------------------------------------
// MCA linear attention, fp32, FFMA2 register-tiled GEMMs.
// R7: 256-thread blocks, 64-pixel tiles, ~85KB smem -> 2 blocks/SM so barrier
// stalls and phase tails of one block overlap with compute of the other.
// ---------------------------------------------------------------------------

#define DINL __device__ __forceinline__
typedef unsigned long long u64;

namespace mca {

constexpr int Bn = 8;
constexpr int Np = 25600;
constexpr int TILE = 64;            // pixels per tile
constexpr int TPB = 256;
constexpr int GRID = 296;           // 2 blocks per SM
constexpr int TILES_TOTAL = 3200;   // Bn*Np/TILE
constexpr int TPBATCH = 400;        // tiles per batch
constexpr int XP = 66;              // u64 pitch for packed activations (64 px)
constexpr int KP = 68;              // f32 pitch for k/v staging
constexpr float EPSV = 1e-6f;

__device__ float g_attn[Bn * 64 * 8];   // [b][pm][c]  (atomic accum)
__device__ float g_ksum_raw[Bn * 64];
__device__ float g_ksum[Bn * 64];       // +eps
__device__ float g_W2[Bn * 4096];       // dense packed; u64 view: [b*2048 + k2*64 + o]

DINL u64 pk2(float lo, float hi) {
    u64 r; asm("mov.b64 %0, {%1, %2};" : "=l"(r) : "f"(lo), "f"(hi)); return r;
}
DINL void upk2(u64 v, float& lo, float& hi) {
    asm("mov.b64 {%0, %1}, %2;" : "=f"(lo), "=f"(hi) : "l"(v));
}
DINL u64 ffma2(u64 a, u64 b, u64 c) {
    u64 d; asm("fma.rn.f32x2 %0, %1, %2, %3;" : "=l"(d) : "l"(a), "l"(b), "l"(c));
    return d;
}
DINL u64 fmul2(u64 a, u64 b) {
    u64 d; asm("mul.rn.f32x2 %0, %1, %2;" : "=l"(d) : "l"(a), "l"(b));
    return d;
}
DINL float softplus(float x) {
    return fmaxf(x, 0.0f) + log1pf(__expf(-fabsf(x)));
}

// ---------------------------------------------------------------------------
__global__ void zero_scratch() {
    int i = blockIdx.x * blockDim.x + threadIdx.x;
    int stride = gridDim.x * blockDim.x;
    for (int j = i; j < Bn * 64 * 8; j += stride) g_attn[j] = 0.0f;
    for (int j = i; j < Bn * 64; j += stride) g_ksum_raw[j] = 0.0f;
}

// ---------------------------------------------------------------------------
// pass1 smem (u64-first):
//   sW [4096] u64, sX [32*66=2112] u64 (aliased by sRed in flush),
//   sKV [128*68] f32, sb [128] f32        total ~85KB -> 2 blocks/SM
// ---------------------------------------------------------------------------
__global__ __launch_bounds__(TPB, 2)
void pass1(const float* __restrict__ low,
           const float* __restrict__ wk, const float* __restrict__ bk,
           const float* __restrict__ wv, const float* __restrict__ bv) {
    extern __shared__ u64 smu[];
    u64*   sW  = smu;                      // 4096
    u64*   sX  = smu + 4096;               // 2112
    float* sKV = (float*)(smu + 4096 + 2112);  // 128*KP
    float* sb  = sKV + 128 * KP;           // 128
    float* sRed = (float*)sX;              // alias (flush only; 2304 <= 4224 f32)

    const int tid = threadIdx.x;
    const int blk = blockIdx.x;
    const int t0 = (int)(((long long)blk * TILES_TOTAL) / GRID);
    const int t1 = (int)(((long long)(blk + 1) * TILES_TOTAL) / GRID);

    for (int i = tid; i < 4096; i += TPB) {
        int k2 = i >> 7, r = i & 127;
        const float* Wr = (r < 64) ? (wk + r * 64) : (wv + (r - 64) * 64);
        sW[k2 * 128 + r] = pk2(Wr[2 * k2], Wr[2 * k2 + 1]);
    }
    if (tid < 64) sb[tid] = bk[tid];
    else if (tid < 128) sb[tid] = bv[tid - 64];

    // GEMM tile: 8 oc rows x 4 px per thread (px = 2*pg+{0,1} + 32*jj)
    const int ocg = tid >> 4;          // 0..15
    const int r0  = ocg * 8;
    const int pg  = tid & 15;
    const bool isK = (r0 < 64);

    // stage-B identity: 64 pm x 4 slices of 16 px
    const int pm = tid & 63, slice = tid >> 6, p8 = pm & 56;
    float racc[8] = {0, 0, 0, 0, 0, 0, 0, 0};
    float rks = 0.0f;
    int bprev = t0 / TPBATCH;

#define P1_FLUSH(BIDX)                                                        \
    do {                                                                      \
        __syncthreads();                                                      \
        _Pragma("unroll")                                                     \
        for (int c = 0; c < 8; c++) sRed[tid * 9 + c] = racc[c];              \
        sRed[tid * 9 + 8] = rks;                                              \
        __syncthreads();                                                      \
        if (tid < 64) {                                                       \
            float s[9] = {0, 0, 0, 0, 0, 0, 0, 0, 0};                         \
            _Pragma("unroll")                                                 \
            for (int sl = 0; sl < 4; sl++) {                                  \
                const float* p = sRed + (sl * 64 + tid) * 9;                  \
                _Pragma("unroll")                                             \
                for (int c = 0; c < 9; c++) s[c] += p[c];                     \
            }                                                                 \
            _Pragma("unroll")                                                 \
            for (int c = 0; c < 8; c++)                                       \
                atomicAdd(g_attn + ((BIDX) * 64 + tid) * 8 + c, s[c]);        \
            atomicAdd(g_ksum_raw + (BIDX) * 64 + tid, s[8]);                  \
        }                                                                     \
        _Pragma("unroll")                                                     \
        for (int c = 0; c < 8; c++) racc[c] = 0.0f;                           \
        rks = 0.0f;                                                           \
    } while (0)

    for (int t = t0; t < t1; ++t) {
        const int b = t / TPBATCH;
        if (b != bprev) { P1_FLUSH(bprev); bprev = b; }
        const int n0 = (t % TPBATCH) * TILE;
        const float* xb = low + ((size_t)b * 64) * Np + n0;

        __syncthreads();   // prior sX/sKV readers done
#pragma unroll
        for (int it = 0; it < 8; it++) {
            int idx = tid + TPB * it;          // 0..2047
            int k2 = idx >> 6, px = idx & 63;
            sX[k2 * XP + px] =
                pk2(xb[(size_t)(2 * k2) * Np + px], xb[(size_t)(2 * k2 + 1) * Np + px]);
        }
        __syncthreads();

        // ---- GEMM: 128 rows x 64 px over 32 k2 ----
        u64 acc[32];
#pragma unroll
        for (int i = 0; i < 32; i++) acc[i] = 0ull;
#pragma unroll 4
        for (int k2 = 0; k2 < 32; k2++) {
            const ulonglong2* wp = (const ulonglong2*)(sW + k2 * 128 + r0);
            ulonglong2 w01 = wp[0], w23 = wp[1], w45 = wp[2], w67 = wp[3];
            u64 w2r[8] = {w01.x, w01.y, w23.x, w23.y, w45.x, w45.y, w67.x, w67.y};
            ulonglong2 xa = *(const ulonglong2*)(sX + k2 * XP + 2 * pg);
            ulonglong2 xc = *(const ulonglong2*)(sX + k2 * XP + 32 + 2 * pg);
            u64 x2r[4] = {xa.x, xa.y, xc.x, xc.y};
#pragma unroll
            for (int oi = 0; oi < 8; oi++)
#pragma unroll
                for (int j = 0; j < 4; j++)
                    acc[oi * 4 + j] = ffma2(w2r[oi], x2r[j], acc[oi * 4 + j]);
        }

        // epilogue -> sKV (paired STS.64)
#pragma unroll
        for (int oi = 0; oi < 8; oi++) {
            const int r = r0 + oi;
            const float bias = sb[r];
#pragma unroll
            for (int jj = 0; jj < 2; jj++) {
                float lo0, hi0, lo1, hi1;
                upk2(acc[oi * 4 + 2 * jj], lo0, hi0);
                upk2(acc[oi * 4 + 2 * jj + 1], lo1, hi1);
                float v0 = lo0 + hi0 + bias;
                float v1 = lo1 + hi1 + bias;
                if (isK) { v0 = softplus(v0); v1 = softplus(v1); }
                *(u64*)(sKV + r * KP + 2 * pg + 32 * jj) = pk2(v0, v1);
            }
        }
        __syncthreads();

        // ---- stage B: attn reduce (float4 reads) ----
        const float* kr = sKV + pm * KP + slice * 16;
        const float* vr = sKV + (64 + p8) * KP + slice * 16;
#pragma unroll
        for (int ii = 0; ii < 4; ii++) {
            float4 kq = *(const float4*)(kr + 4 * ii);
            rks += (kq.x + kq.y) + (kq.z + kq.w);
#pragma unroll
            for (int c = 0; c < 8; c++) {
                float4 vq = *(const float4*)(vr + c * KP + 4 * ii);
                racc[c] += kq.x * vq.x + kq.y * vq.y + kq.z * vq.z + kq.w * vq.w;
            }
        }
    }
    P1_FLUSH(bprev);
#undef P1_FLUSH
}

// ---------------------------------------------------------------------------
__global__ __launch_bounds__(512, 1)
void prep(const float* __restrict__ wo) {
    __shared__ float sA[512];
    const int tid = threadIdx.x;
    const int b = blockIdx.x;
    sA[tid] = g_attn[b * 512 + tid];
    if (tid < 64) g_ksum[b * 64 + tid] = g_ksum_raw[b * 64 + tid] + EPSV;
    __syncthreads();
    for (int idx = tid; idx < 4096; idx += 512) {
        int o = idx >> 6, pm = idx & 63;
        const float* wr = wo + o * 64 + (pm & 56);
        const float* ar = sA + pm * 8;
        float acc = 0.0f;
#pragma unroll
        for (int c = 0; c < 8; c++) acc += wr[c] * ar[c];
        g_W2[b * 4096 + ((pm >> 1) * 64 + o) * 2 + (pm & 1)] = acc;
    }
}

// ---------------------------------------------------------------------------
// pass2 smem: sWq[2048] sW2[2048] sXh[2112] sXl[2112] sQ[2112] u64,
//             sks2[32] u64, sbq[64] f32, sbo[64] f32    total ~84KB
// ---------------------------------------------------------------------------
__global__ __launch_bounds__(TPB, 2)
void pass2(const float* __restrict__ high, const float* __restrict__ low,
           const float* __restrict__ wqh, const float* __restrict__ bqh,
           const float* __restrict__ wql, const float* __restrict__ bql,
           const float* __restrict__ bo, float* __restrict__ out) {
    extern __shared__ u64 smu[];
    u64*   sWq  = smu;                         // 2048
    u64*   sW2  = smu + 2048;                  // 2048
    u64*   sXh  = smu + 4096;                  // 2112
    u64*   sXl  = smu + 4096 + 2112;           // 2112
    u64*   sQ   = smu + 4096 + 2 * 2112;       // 2112
    u64*   sks2 = smu + 4096 + 3 * 2112;       // 32
    float* sbq  = (float*)(sks2 + 32);         // 64
    float* sbo  = sbq + 64;                    // 64

    const int tid = threadIdx.x;
    const int blk = blockIdx.x;
    const int t0 = (int)(((long long)blk * TILES_TOTAL) / GRID);
    const int t1 = (int)(((long long)(blk + 1) * TILES_TOTAL) / GRID);

    for (int i = tid; i < 2048; i += TPB) {
        int k2 = i >> 6, r = i & 63;
        const float* Wr = (r < 32) ? (wqh + r * 64) : (wql + (r - 32) * 64);
        sWq[k2 * 64 + r] = pk2(Wr[2 * k2], Wr[2 * k2 + 1]);
    }
    if (tid < 32) sbq[tid] = bqh[tid];
    else if (tid < 64) sbq[tid] = bql[tid - 32];
    else if (tid < 128) sbo[tid - 64] = bo[tid - 64];

    // GEMM1: 8 rows x 2 px; halves on different inputs
    const int half = tid >> 7;               // 0 = high rows 0..31, 1 = low rows 32..63
    const int t7   = tid & 127;
    const int ocg1 = t7 >> 5;                // 0..3
    const int r1   = half * 32 + ocg1 * 8;
    const int pg1  = t7 & 31;                // px pair 2*pg1
    // GEMM2: 8 rows x 2 px
    const int ocg2 = tid >> 5;               // 0..7
    const int r2   = ocg2 * 8;
    const int pg2  = tid & 31;

    int bprev = -1;

    for (int t = t0; t < t1; ++t) {
        const int b = t / TPBATCH;
        if (b != bprev) {
            __syncthreads();   // prior GEMM2/norm readers of sW2/sks2 done
            const u64* gW2 = (const u64*)g_W2 + (size_t)b * 2048;
            for (int i = tid; i < 2048; i += TPB) sW2[i] = gW2[i];
            if (tid < 32)
                sks2[tid] = pk2(g_ksum[b * 64 + 2 * tid], g_ksum[b * 64 + 2 * tid + 1]);
            bprev = b;
        }
        const int n0 = (t % TPBATCH) * TILE;
        const float* xh = high + ((size_t)b * 64) * Np + n0;
        const float* xl = low  + ((size_t)b * 64) * Np + n0;

        __syncthreads();
#pragma unroll
        for (int it = 0; it < 8; it++) {
            int idx = tid + TPB * it;          // 0..2047
            int k2 = idx >> 6, px = idx & 63;
            sXh[k2 * XP + px] =
                pk2(xh[(size_t)(2 * k2) * Np + px], xh[(size_t)(2 * k2 + 1) * Np + px]);
            sXl[k2 * XP + px] =
                pk2(xl[(size_t)(2 * k2) * Np + px], xl[(size_t)(2 * k2 + 1) * Np + px]);
        }
        __syncthreads();

        // ---- GEMM1: q = softplus(Wq @ X) -> sQ packed ----
        {
            const u64* sXin = half ? sXl : sXh;
            u64 acc[16];
#pragma unroll
            for (int i = 0; i < 16; i++) acc[i] = 0ull;
#pragma unroll 4
            for (int k2 = 0; k2 < 32; k2++) {
                const ulonglong2* wp = (const ulonglong2*)(sWq + k2 * 64 + r1);
                ulonglong2 w01 = wp[0], w23 = wp[1], w45 = wp[2], w67 = wp[3];
                u64 w2r[8] = {w01.x, w01.y, w23.x, w23.y, w45.x, w45.y, w67.x, w67.y};
                ulonglong2 xa = *(const ulonglong2*)(sXin + k2 * XP + 2 * pg1);
#pragma unroll
                for (int oi = 0; oi < 8; oi++) {
                    acc[oi * 2 + 0] = ffma2(w2r[oi], xa.x, acc[oi * 2 + 0]);
                    acc[oi * 2 + 1] = ffma2(w2r[oi], xa.y, acc[oi * 2 + 1]);
                }
            }
#pragma unroll
            for (int oi2 = 0; oi2 < 4; oi2++) {
                const int ra = r1 + 2 * oi2;
                const float ba0 = sbq[ra], ba1 = sbq[ra + 1];
                float lo, hi;
                upk2(acc[(2 * oi2) * 2 + 0], lo, hi);     float v00 = softplus(lo + hi + ba0);
                upk2(acc[(2 * oi2) * 2 + 1], lo, hi);     float v01 = softplus(lo + hi + ba0);
                upk2(acc[(2 * oi2 + 1) * 2 + 0], lo, hi); float v10 = softplus(lo + hi + ba1);
                upk2(acc[(2 * oi2 + 1) * 2 + 1], lo, hi); float v11 = softplus(lo + hi + ba1);
                ulonglong2 st;
                st.x = pk2(v00, v10);
                st.y = pk2(v01, v11);
                *(ulonglong2*)(sQ + (ra >> 1) * XP + 2 * pg1) = st;
            }
        }
        __syncthreads();

        // ---- fused norm + in-place rescale: each (h,px) unit owns 4 sQ words ----
#pragma unroll
        for (int rr = 0; rr < 2; rr++) {
            int it = tid + TPB * rr;           // 0..511
            int h = it >> 6, px = it & 63;
            u64 q0 = sQ[(h * 4 + 0) * XP + px];
            u64 q1 = sQ[(h * 4 + 1) * XP + px];
            u64 q2 = sQ[(h * 4 + 2) * XP + px];
            u64 q3 = sQ[(h * 4 + 3) * XP + px];
            u64 a = ffma2(q0, sks2[h * 4 + 0], 0ull);
            a = ffma2(q1, sks2[h * 4 + 1], a);
            a = ffma2(q2, sks2[h * 4 + 2], a);
            a = ffma2(q3, sks2[h * 4 + 3], a);
            float lo, hi; upk2(a, lo, hi);
            float inv = 1.0f / (lo + hi);
            u64 iv = pk2(inv, inv);
            sQ[(h * 4 + 0) * XP + px] = fmul2(q0, iv);
            sQ[(h * 4 + 1) * XP + px] = fmul2(q1, iv);
            sQ[(h * 4 + 2) * XP + px] = fmul2(q2, iv);
            sQ[(h * 4 + 3) * XP + px] = fmul2(q3, iv);
        }
        __syncthreads();

        // ---- GEMM2: out = W2 @ q' + bo ----
        {
            u64 acc[16];
#pragma unroll
            for (int i = 0; i < 16; i++) acc[i] = 0ull;
#pragma unroll 4
            for (int k2 = 0; k2 < 32; k2++) {
                const ulonglong2* wp = (const ulonglong2*)(sW2 + k2 * 64 + r2);
                ulonglong2 w01 = wp[0], w23 = wp[1], w45 = wp[2], w67 = wp[3];
                u64 w2r[8] = {w01.x, w01.y, w23.x, w23.y, w45.x, w45.y, w67.x, w67.y};
                ulonglong2 xa = *(const ulonglong2*)(sQ + k2 * XP + 2 * pg2);
#pragma unroll
                for (int oi = 0; oi < 8; oi++) {
                    acc[oi * 2 + 0] = ffma2(w2r[oi], xa.x, acc[oi * 2 + 0]);
                    acc[oi * 2 + 1] = ffma2(w2r[oi], xa.y, acc[oi * 2 + 1]);
                }
            }
            float* ob = out + ((size_t)b * 64) * Np + n0;
#pragma unroll
            for (int oi = 0; oi < 8; oi++) {
                const int r = r2 + oi;
                const float bias = sbo[r];
                float lo0, hi0, lo1, hi1;
                upk2(acc[oi * 2 + 0], lo0, hi0);
                upk2(acc[oi * 2 + 1], lo1, hi1);
                *(float2*)(ob + (size_t)r * Np + 2 * pg2) =
                    make_float2(lo0 + hi0 + bias, lo1 + hi1 + bias);
            }
        }
    }
}

constexpr int SMEM1 = (4096 + 2112) * 8 + (128 * KP + 128) * 4;             // 84,992
constexpr int SMEM2 = (4096 + 3 * 2112 + 32) * 8 + 128 * 4;                 // 84,224

}  // namespace mca

// ---------------------------------------------------------------------------
extern "C" void kernel_launch(void* const* d_in, const int* in_sizes, int n_in,
                              void* d_out, int out_size) {
    using namespace mca;
    (void)in_sizes; (void)n_in; (void)out_size;

    const float* high = (const float*)d_in[0];
    const float* low  = (const float*)d_in[1];
    const float* wqh  = (const float*)d_in[2];
    const float* bqh  = (const float*)d_in[3];
    const float* wql  = (const float*)d_in[4];
    const float* bql  = (const float*)d_in[5];
    const float* wk   = (const float*)d_in[6];
    const float* bk   = (const float*)d_in[7];
    const float* wv   = (const float*)d_in[8];
    const float* bv   = (const float*)d_in[9];
    const float* wo   = (const float*)d_in[10];
    const float* bo   = (const float*)d_in[11];
    float* out = (float*)d_out;

    cudaFuncSetAttribute(pass1, cudaFuncAttributeMaxDynamicSharedMemorySize, SMEM1);
    cudaFuncSetAttribute(pass2, cudaFuncAttributeMaxDynamicSharedMemorySize, SMEM2);

    zero_scratch<<<8, 512>>>();
    pass1<<<GRID, TPB, SMEM1>>>(low, wk, bk, wv, bv);
    prep<<<Bn, 512>>>(wo);
    pass2<<<GRID, TPB, SMEM2>>>(high, low, wqh, bqh, wql, bql, bo, out);
}

// round 9
// speedup vs baseline: 1.6533x; 1.0449x over previous
#include <cuda_runtime.h>

// ---------------------------------------------------------------------------
// MCA linear attention, fp32, FFMA2 register-tiled GEMMs.
// R8: fast intrinsic softplus (MUFU-based, ~9 instr vs log1pf ~25-30);
//     pass2 GEMMs widened to 8 rows x 4 px (128 active threads, wf/FMA2
//     0.5 -> 0.375) with the co-resident block covering idle phases.
// ---------------------------------------------------------------------------

#define DINL __device__ __forceinline__
typedef unsigned long long u64;

namespace mca {

constexpr int Bn = 8;
constexpr int Np = 25600;
constexpr int TILE = 64;            // pixels per tile
constexpr int TPB = 256;
constexpr int GRID = 296;           // 2 blocks per SM
constexpr int TILES_TOTAL = 3200;   // Bn*Np/TILE
constexpr int TPBATCH = 400;        // tiles per batch
constexpr int XP = 66;              // u64 pitch for packed activations (64 px)
constexpr int KP = 68;              // f32 pitch for k/v staging
constexpr float EPSV = 1e-6f;

__device__ float g_attn[Bn * 64 * 8];   // [b][pm][c]  (atomic accum)
__device__ float g_ksum_raw[Bn * 64];
__device__ float g_ksum[Bn * 64];       // +eps
__device__ float g_W2[Bn * 4096];       // dense packed; u64 view: [b*2048 + k2*64 + o]

DINL u64 pk2(float lo, float hi) {
    u64 r; asm("mov.b64 %0, {%1, %2};" : "=l"(r) : "f"(lo), "f"(hi)); return r;
}
DINL void upk2(u64 v, float& lo, float& hi) {
    asm("mov.b64 {%0, %1}, %2;" : "=f"(lo), "=f"(hi) : "l"(v));
}
DINL u64 ffma2(u64 a, u64 b, u64 c) {
    u64 d; asm("fma.rn.f32x2 %0, %1, %2, %3;" : "=l"(d) : "l"(a), "l"(b), "l"(c));
    return d;
}
DINL u64 fmul2(u64 a, u64 b) {
    u64 d; asm("mul.rn.f32x2 %0, %1, %2;" : "=l"(d) : "l"(a), "l"(b));
    return d;
}
// Fast stable softplus: arg of __logf is in (1,2], no overflow anywhere.
// MUFU.EX2 + MUFU.LG2 path, ~9 instr; rel err ~1e-6 (threshold 1e-3).
DINL float softplus(float x) {
    float e = __expf(-fabsf(x));
    return fmaxf(x, 0.0f) + __logf(1.0f + e);
}

// ---------------------------------------------------------------------------
__global__ void zero_scratch() {
    int i = blockIdx.x * blockDim.x + threadIdx.x;
    int stride = gridDim.x * blockDim.x;
    for (int j = i; j < Bn * 64 * 8; j += stride) g_attn[j] = 0.0f;
    for (int j = i; j < Bn * 64; j += stride) g_ksum_raw[j] = 0.0f;
}

// ---------------------------------------------------------------------------
// pass1 smem (u64-first):
//   sW [4096] u64, sX [32*66=2112] u64 (aliased by sRed in flush),
//   sKV [128*68] f32, sb [128] f32        total ~85KB -> 2 blocks/SM
// ---------------------------------------------------------------------------
__global__ __launch_bounds__(TPB, 2)
void pass1(const float* __restrict__ low,
           const float* __restrict__ wk, const float* __restrict__ bk,
           const float* __restrict__ wv, const float* __restrict__ bv) {
    extern __shared__ u64 smu[];
    u64*   sW  = smu;                      // 4096
    u64*   sX  = smu + 4096;               // 2112
    float* sKV = (float*)(smu + 4096 + 2112);  // 128*KP
    float* sb  = sKV + 128 * KP;           // 128
    float* sRed = (float*)sX;              // alias (flush only)

    const int tid = threadIdx.x;
    const int blk = blockIdx.x;
    const int t0 = (int)(((long long)blk * TILES_TOTAL) / GRID);
    const int t1 = (int)(((long long)(blk + 1) * TILES_TOTAL) / GRID);

    for (int i = tid; i < 4096; i += TPB) {
        int k2 = i >> 7, r = i & 127;
        const float* Wr = (r < 64) ? (wk + r * 64) : (wv + (r - 64) * 64);
        sW[k2 * 128 + r] = pk2(Wr[2 * k2], Wr[2 * k2 + 1]);
    }
    if (tid < 64) sb[tid] = bk[tid];
    else if (tid < 128) sb[tid] = bv[tid - 64];

    // GEMM tile: 8 oc rows x 4 px per thread (px = 2*pg+{0,1} + 32*jj)
    const int ocg = tid >> 4;          // 0..15
    const int r0  = ocg * 8;
    const int pg  = tid & 15;
    const bool isK = (r0 < 64);

    // stage-B identity: 64 pm x 4 slices of 16 px
    const int pm = tid & 63, slice = tid >> 6, p8 = pm & 56;
    float racc[8] = {0, 0, 0, 0, 0, 0, 0, 0};
    float rks = 0.0f;
    int bprev = t0 / TPBATCH;

#define P1_FLUSH(BIDX)                                                        \
    do {                                                                      \
        __syncthreads();                                                      \
        _Pragma("unroll")                                                     \
        for (int c = 0; c < 8; c++) sRed[tid * 9 + c] = racc[c];              \
        sRed[tid * 9 + 8] = rks;                                              \
        __syncthreads();                                                      \
        if (tid < 64) {                                                       \
            float s[9] = {0, 0, 0, 0, 0, 0, 0, 0, 0};                         \
            _Pragma("unroll")                                                 \
            for (int sl = 0; sl < 4; sl++) {                                  \
                const float* p = sRed + (sl * 64 + tid) * 9;                  \
                _Pragma("unroll")                                             \
                for (int c = 0; c < 9; c++) s[c] += p[c];                     \
            }                                                                 \
            _Pragma("unroll")                                                 \
            for (int c = 0; c < 8; c++)                                       \
                atomicAdd(g_attn + ((BIDX) * 64 + tid) * 8 + c, s[c]);        \
            atomicAdd(g_ksum_raw + (BIDX) * 64 + tid, s[8]);                  \
        }                                                                     \
        _Pragma("unroll")                                                     \
        for (int c = 0; c < 8; c++) racc[c] = 0.0f;                           \
        rks = 0.0f;                                                           \
    } while (0)

    for (int t = t0; t < t1; ++t) {
        const int b = t / TPBATCH;
        if (b != bprev) { P1_FLUSH(bprev); bprev = b; }
        const int n0 = (t % TPBATCH) * TILE;
        const float* xb = low + ((size_t)b * 64) * Np + n0;

        __syncthreads();   // prior sX/sKV readers done
#pragma unroll
        for (int it = 0; it < 8; it++) {
            int idx = tid + TPB * it;          // 0..2047
            int k2 = idx >> 6, px = idx & 63;
            sX[k2 * XP + px] =
                pk2(xb[(size_t)(2 * k2) * Np + px], xb[(size_t)(2 * k2 + 1) * Np + px]);
        }
        __syncthreads();

        // ---- GEMM: 128 rows x 64 px over 32 k2 ----
        u64 acc[32];
#pragma unroll
        for (int i = 0; i < 32; i++) acc[i] = 0ull;
#pragma unroll 4
        for (int k2 = 0; k2 < 32; k2++) {
            const ulonglong2* wp = (const ulonglong2*)(sW + k2 * 128 + r0);
            ulonglong2 w01 = wp[0], w23 = wp[1], w45 = wp[2], w67 = wp[3];
            u64 w2r[8] = {w01.x, w01.y, w23.x, w23.y, w45.x, w45.y, w67.x, w67.y};
            ulonglong2 xa = *(const ulonglong2*)(sX + k2 * XP + 2 * pg);
            ulonglong2 xc = *(const ulonglong2*)(sX + k2 * XP + 32 + 2 * pg);
            u64 x2r[4] = {xa.x, xa.y, xc.x, xc.y};
#pragma unroll
            for (int oi = 0; oi < 8; oi++)
#pragma unroll
                for (int j = 0; j < 4; j++)
                    acc[oi * 4 + j] = ffma2(w2r[oi], x2r[j], acc[oi * 4 + j]);
        }

        // epilogue -> sKV (paired STS.64)
#pragma unroll
        for (int oi = 0; oi < 8; oi++) {
            const int r = r0 + oi;
            const float bias = sb[r];
#pragma unroll
            for (int jj = 0; jj < 2; jj++) {
                float lo0, hi0, lo1, hi1;
                upk2(acc[oi * 4 + 2 * jj], lo0, hi0);
                upk2(acc[oi * 4 + 2 * jj + 1], lo1, hi1);
                float v0 = lo0 + hi0 + bias;
                float v1 = lo1 + hi1 + bias;
                if (isK) { v0 = softplus(v0); v1 = softplus(v1); }
                *(u64*)(sKV + r * KP + 2 * pg + 32 * jj) = pk2(v0, v1);
            }
        }
        __syncthreads();

        // ---- stage B: attn reduce (float4 reads) ----
        const float* kr = sKV + pm * KP + slice * 16;
        const float* vr = sKV + (64 + p8) * KP + slice * 16;
#pragma unroll
        for (int ii = 0; ii < 4; ii++) {
            float4 kq = *(const float4*)(kr + 4 * ii);
            rks += (kq.x + kq.y) + (kq.z + kq.w);
#pragma unroll
            for (int c = 0; c < 8; c++) {
                float4 vq = *(const float4*)(vr + c * KP + 4 * ii);
                racc[c] += kq.x * vq.x + kq.y * vq.y + kq.z * vq.z + kq.w * vq.w;
            }
        }
    }
    P1_FLUSH(bprev);
#undef P1_FLUSH
}

// ---------------------------------------------------------------------------
__global__ __launch_bounds__(512, 1)
void prep(const float* __restrict__ wo) {
    __shared__ float sA[512];
    const int tid = threadIdx.x;
    const int b = blockIdx.x;
    sA[tid] = g_attn[b * 512 + tid];
    if (tid < 64) g_ksum[b * 64 + tid] = g_ksum_raw[b * 64 + tid] + EPSV;
    __syncthreads();
    for (int idx = tid; idx < 4096; idx += 512) {
        int o = idx >> 6, pm = idx & 63;
        const float* wr = wo + o * 64 + (pm & 56);
        const float* ar = sA + pm * 8;
        float acc = 0.0f;
#pragma unroll
        for (int c = 0; c < 8; c++) acc += wr[c] * ar[c];
        g_W2[b * 4096 + ((pm >> 1) * 64 + o) * 2 + (pm & 1)] = acc;
    }
}

// ---------------------------------------------------------------------------
// pass2 smem: sWq[2048] sW2[2048] sXh[2112] sXl[2112] sQ[2112] u64,
//             sks2[32] u64, sbq[64] f32, sbo[64] f32    total ~84KB
// GEMM phases use 128 threads at 8 rows x 4 px (wf/FMA2 = 0.375).
// ---------------------------------------------------------------------------
__global__ __launch_bounds__(TPB, 2)
void pass2(const float* __restrict__ high, const float* __restrict__ low,
           const float* __restrict__ wqh, const float* __restrict__ bqh,
           const float* __restrict__ wql, const float* __restrict__ bql,
           const float* __restrict__ bo, float* __restrict__ out) {
    extern __shared__ u64 smu[];
    u64*   sWq  = smu;                         // 2048
    u64*   sW2  = smu + 2048;                  // 2048
    u64*   sXh  = smu + 4096;                  // 2112
    u64*   sXl  = smu + 4096 + 2112;           // 2112
    u64*   sQ   = smu + 4096 + 2 * 2112;       // 2112
    u64*   sks2 = smu + 4096 + 3 * 2112;       // 32
    float* sbq  = (float*)(sks2 + 32);         // 64
    float* sbo  = sbq + 64;                    // 64

    const int tid = threadIdx.x;
    const int blk = blockIdx.x;
    const int t0 = (int)(((long long)blk * TILES_TOTAL) / GRID);
    const int t1 = (int)(((long long)(blk + 1) * TILES_TOTAL) / GRID);

    for (int i = tid; i < 2048; i += TPB) {
        int k2 = i >> 6, r = i & 63;
        const float* Wr = (r < 32) ? (wqh + r * 64) : (wql + (r - 32) * 64);
        sWq[k2 * 64 + r] = pk2(Wr[2 * k2], Wr[2 * k2 + 1]);
    }
    if (tid < 32) sbq[tid] = bqh[tid];
    else if (tid < 64) sbq[tid] = bql[tid - 32];
    else if (tid < 128) sbo[tid - 64] = bo[tid - 64];

    // GEMM coords (threads 0..127 active): 8 rows x 4 px
    const int ocg = (tid & 127) >> 4;        // 0..7
    const int rG  = ocg * 8;                 // rows rG..rG+7 (GEMM1: 0..31 high, 32..63 low)
    const int pg  = tid & 15;                // px = 2*pg + {0,1} + 32*jj
    const bool gActive = (tid < 128);

    int bprev = -1;

    for (int t = t0; t < t1; ++t) {
        const int b = t / TPBATCH;
        if (b != bprev) {
            __syncthreads();   // prior GEMM2/norm readers of sW2/sks2 done
            const u64* gW2 = (const u64*)g_W2 + (size_t)b * 2048;
            for (int i = tid; i < 2048; i += TPB) sW2[i] = gW2[i];
            if (tid < 32)
                sks2[tid] = pk2(g_ksum[b * 64 + 2 * tid], g_ksum[b * 64 + 2 * tid + 1]);
            bprev = b;
        }
        const int n0 = (t % TPBATCH) * TILE;
        const float* xh = high + ((size_t)b * 64) * Np + n0;
        const float* xl = low  + ((size_t)b * 64) * Np + n0;

        __syncthreads();
#pragma unroll
        for (int it = 0; it < 8; it++) {
            int idx = tid + TPB * it;          // 0..2047
            int k2 = idx >> 6, px = idx & 63;
            sXh[k2 * XP + px] =
                pk2(xh[(size_t)(2 * k2) * Np + px], xh[(size_t)(2 * k2 + 1) * Np + px]);
            sXl[k2 * XP + px] =
                pk2(xl[(size_t)(2 * k2) * Np + px], xl[(size_t)(2 * k2 + 1) * Np + px]);
        }
        __syncthreads();

        // ---- GEMM1: q = softplus(Wq @ X) -> sQ packed (threads 0..127) ----
        if (gActive) {
            const u64* sXin = (rG < 32) ? sXh : sXl;
            u64 acc[32];
#pragma unroll
            for (int i = 0; i < 32; i++) acc[i] = 0ull;
#pragma unroll 4
            for (int k2 = 0; k2 < 32; k2++) {
                const ulonglong2* wp = (const ulonglong2*)(sWq + k2 * 64 + rG);
                ulonglong2 w01 = wp[0], w23 = wp[1], w45 = wp[2], w67 = wp[3];
                u64 w2r[8] = {w01.x, w01.y, w23.x, w23.y, w45.x, w45.y, w67.x, w67.y};
                ulonglong2 xa = *(const ulonglong2*)(sXin + k2 * XP + 2 * pg);
                ulonglong2 xc = *(const ulonglong2*)(sXin + k2 * XP + 32 + 2 * pg);
                u64 x2r[4] = {xa.x, xa.y, xc.x, xc.y};
#pragma unroll
                for (int oi = 0; oi < 8; oi++)
#pragma unroll
                    for (int j = 0; j < 4; j++)
                        acc[oi * 4 + j] = ffma2(w2r[oi], x2r[j], acc[oi * 4 + j]);
            }
            // epilogue: bias + softplus, pack row-pairs into sQ
#pragma unroll
            for (int oi2 = 0; oi2 < 4; oi2++) {
                const int ra = rG + 2 * oi2;
                const float ba0 = sbq[ra], ba1 = sbq[ra + 1];
#pragma unroll
                for (int jj = 0; jj < 2; jj++) {
                    float lo, hi;
                    upk2(acc[(2 * oi2) * 4 + 2 * jj], lo, hi);
                    float v00 = softplus(lo + hi + ba0);
                    upk2(acc[(2 * oi2) * 4 + 2 * jj + 1], lo, hi);
                    float v01 = softplus(lo + hi + ba0);
                    upk2(acc[(2 * oi2 + 1) * 4 + 2 * jj], lo, hi);
                    float v10 = softplus(lo + hi + ba1);
                    upk2(acc[(2 * oi2 + 1) * 4 + 2 * jj + 1], lo, hi);
                    float v11 = softplus(lo + hi + ba1);
                    ulonglong2 st;
                    st.x = pk2(v00, v10);
                    st.y = pk2(v01, v11);
                    *(ulonglong2*)(sQ + (ra >> 1) * XP + 32 * jj + 2 * pg) = st;
                }
            }
        }
        __syncthreads();

        // ---- fused norm + in-place rescale (all 256 threads) ----
#pragma unroll
        for (int rr = 0; rr < 2; rr++) {
            int it = tid + TPB * rr;           // 0..511
            int h = it >> 6, px = it & 63;
            u64 q0 = sQ[(h * 4 + 0) * XP + px];
            u64 q1 = sQ[(h * 4 + 1) * XP + px];
            u64 q2 = sQ[(h * 4 + 2) * XP + px];
            u64 q3 = sQ[(h * 4 + 3) * XP + px];
            u64 a = ffma2(q0, sks2[h * 4 + 0], 0ull);
            a = ffma2(q1, sks2[h * 4 + 1], a);
            a = ffma2(q2, sks2[h * 4 + 2], a);
            a = ffma2(q3, sks2[h * 4 + 3], a);
            float lo, hi; upk2(a, lo, hi);
            float inv = 1.0f / (lo + hi);
            u64 iv = pk2(inv, inv);
            sQ[(h * 4 + 0) * XP + px] = fmul2(q0, iv);
            sQ[(h * 4 + 1) * XP + px] = fmul2(q1, iv);
            sQ[(h * 4 + 2) * XP + px] = fmul2(q2, iv);
            sQ[(h * 4 + 3) * XP + px] = fmul2(q3, iv);
        }
        __syncthreads();

        // ---- GEMM2: out = W2 @ q' + bo (threads 0..127) ----
        if (gActive) {
            u64 acc[32];
#pragma unroll
            for (int i = 0; i < 32; i++) acc[i] = 0ull;
#pragma unroll 4
            for (int k2 = 0; k2 < 32; k2++) {
                const ulonglong2* wp = (const ulonglong2*)(sW2 + k2 * 64 + rG);
                ulonglong2 w01 = wp[0], w23 = wp[1], w45 = wp[2], w67 = wp[3];
                u64 w2r[8] = {w01.x, w01.y, w23.x, w23.y, w45.x, w45.y, w67.x, w67.y};
                ulonglong2 xa = *(const ulonglong2*)(sQ + k2 * XP + 2 * pg);
                ulonglong2 xc = *(const ulonglong2*)(sQ + k2 * XP + 32 + 2 * pg);
                u64 x2r[4] = {xa.x, xa.y, xc.x, xc.y};
#pragma unroll
                for (int oi = 0; oi < 8; oi++)
#pragma unroll
                    for (int j = 0; j < 4; j++)
                        acc[oi * 4 + j] = ffma2(w2r[oi], x2r[j], acc[oi * 4 + j]);
            }
            float* ob = out + ((size_t)b * 64) * Np + n0;
#pragma unroll
            for (int oi = 0; oi < 8; oi++) {
                const int r = rG + oi;
                const float bias = sbo[r];
#pragma unroll
                for (int jj = 0; jj < 2; jj++) {
                    float lo0, hi0, lo1, hi1;
                    upk2(acc[oi * 4 + 2 * jj], lo0, hi0);
                    upk2(acc[oi * 4 + 2 * jj + 1], lo1, hi1);
                    *(float2*)(ob + (size_t)r * Np + 32 * jj + 2 * pg) =
                        make_float2(lo0 + hi0 + bias, lo1 + hi1 + bias);
                }
            }
        }
    }
}

constexpr int SMEM1 = (4096 + 2112) * 8 + (128 * KP + 128) * 4;             // 84,992
constexpr int SMEM2 = (4096 + 3 * 2112 + 32) * 8 + 128 * 4;                 // 84,224

}  // namespace mca

// ---------------------------------------------------------------------------
extern "C" void kernel_launch(void* const* d_in, const int* in_sizes, int n_in,
                              void* d_out, int out_size) {
    using namespace mca;
    (void)in_sizes; (void)n_in; (void)out_size;

    const float* high = (const float*)d_in[0];
    const float* low  = (const float*)d_in[1];
    const float* wqh  = (const float*)d_in[2];
    const float* bqh  = (const float*)d_in[3];
    const float* wql  = (const float*)d_in[4];
    const float* bql  = (const float*)d_in[5];
    const float* wk   = (const float*)d_in[6];
    const float* bk   = (const float*)d_in[7];
    const float* wv   = (const float*)d_in[8];
    const float* bv   = (const float*)d_in[9];
    const float* wo   = (const float*)d_in[10];
    const float* bo   = (const float*)d_in[11];
    float* out = (float*)d_out;

    cudaFuncSetAttribute(pass1, cudaFuncAttributeMaxDynamicSharedMemorySize, SMEM1);
    cudaFuncSetAttribute(pass2, cudaFuncAttributeMaxDynamicSharedMemorySize, SMEM2);

    zero_scratch<<<8, 512>>>();
    pass1<<<GRID, TPB, SMEM1>>>(low, wk, bk, wv, bv);
    prep<<<Bn, 512>>>(wo);
    pass2<<<GRID, TPB, SMEM2>>>(high, low, wqh, bqh, wql, bql, bo, out);
}

// round 12
// speedup vs baseline: 1.6621x; 1.0053x over previous
#include <cuda_runtime.h>

// ---------------------------------------------------------------------------
// MCA linear attention, fp32, FFMA2 register-tiled GEMMs.
// R12 (hedge): pass1 = R10 double-buffered pipeline; pass2 = R9 (known-good).
// ---------------------------------------------------------------------------

#define DINL __device__ __forceinline__
typedef unsigned long long u64;

namespace mca {

constexpr int Bn = 8;
constexpr int Np = 25600;
constexpr int TILE = 64;            // pixels per tile
constexpr int TPB = 256;
constexpr int GRID = 296;           // 2 blocks per SM
constexpr int TILES_TOTAL = 3200;   // Bn*Np/TILE
constexpr int TPBATCH = 400;        // tiles per batch
constexpr int XP = 66;              // u64 pitch for packed activations (64 px)
constexpr int KP = 68;              // f32 pitch for k/v staging
constexpr float EPSV = 1e-6f;

__device__ float g_attn[Bn * 64 * 8];   // [b][pm][c]  (atomic accum)
__device__ float g_ksum_raw[Bn * 64];
__device__ float g_ksum[Bn * 64];       // +eps
__device__ float g_W2[Bn * 4096];       // dense packed; u64 view: [b*2048 + k2*64 + o]

DINL u64 pk2(float lo, float hi) {
    u64 r; asm("mov.b64 %0, {%1, %2};" : "=l"(r) : "f"(lo), "f"(hi)); return r;
}
DINL void upk2(u64 v, float& lo, float& hi) {
    asm("mov.b64 {%0, %1}, %2;" : "=f"(lo), "=f"(hi) : "l"(v));
}
DINL u64 ffma2(u64 a, u64 b, u64 c) {
    u64 d; asm("fma.rn.f32x2 %0, %1, %2, %3;" : "=l"(d) : "l"(a), "l"(b), "l"(c));
    return d;
}
DINL u64 fmul2(u64 a, u64 b) {
    u64 d; asm("mul.rn.f32x2 %0, %1, %2;" : "=l"(d) : "l"(a), "l"(b));
    return d;
}
// Fast stable softplus: arg of __logf is in (1,2], no overflow anywhere.
DINL float softplus(float x) {
    float e = __expf(-fabsf(x));
    return fmaxf(x, 0.0f) + __logf(1.0f + e);
}

// ---------------------------------------------------------------------------
__global__ void zero_scratch() {
    int i = blockIdx.x * blockDim.x + threadIdx.x;
    int stride = gridDim.x * blockDim.x;
    for (int j = i; j < Bn * 64 * 8; j += stride) g_attn[j] = 0.0f;
    for (int j = i; j < Bn * 64; j += stride) g_ksum_raw[j] = 0.0f;
}

// ---------------------------------------------------------------------------
// pass1 smem (u64-first):
//   sW [4096] u64, sX0 [2112] u64, sX1 [2112] u64 (double buffer),
//   sKV [128*68] f32 (aliased by sRed during flush), sb [128]
//   total 101,888 B -> 2 blocks/SM
// ---------------------------------------------------------------------------
__global__ __launch_bounds__(TPB, 2)
void pass1(const float* __restrict__ low,
           const float* __restrict__ wk, const float* __restrict__ bk,
           const float* __restrict__ wv, const float* __restrict__ bv) {
    extern __shared__ u64 smu[];
    u64*   sW  = smu;                          // 4096
    u64*   sX0 = smu + 4096;                   // 2112
    u64*   sX1 = smu + 4096 + 2112;            // 2112
    float* sKV = (float*)(smu + 4096 + 4224);  // 128*KP
    float* sb  = sKV + 128 * KP;               // 128
    float* sRed = sKV;                         // alias (flush only; sKV dead then)

    const int tid = threadIdx.x;
    const int blk = blockIdx.x;
    const int t0 = (int)(((long long)blk * TILES_TOTAL) / GRID);
    const int t1 = (int)(((long long)(blk + 1) * TILES_TOTAL) / GRID);

    for (int i = tid; i < 4096; i += TPB) {
        int k2 = i >> 7, r = i & 127;
        const float* Wr = (r < 64) ? (wk + r * 64) : (wv + (r - 64) * 64);
        sW[k2 * 128 + r] = pk2(Wr[2 * k2], Wr[2 * k2 + 1]);
    }
    if (tid < 64) sb[tid] = bk[tid];
    else if (tid < 128) sb[tid] = bv[tid - 64];

    // prologue: stage tile t0 into buf[t0&1]
    {
        const int bb = t0 / TPBATCH;
        const int n00 = (t0 % TPBATCH) * TILE;
        const float* xb = low + ((size_t)bb * 64) * Np + n00;
        u64* sXc = (t0 & 1) ? sX1 : sX0;
#pragma unroll
        for (int it = 0; it < 8; it++) {
            int idx = tid + TPB * it;
            int k2 = idx >> 6, px = idx & 63;
            sXc[k2 * XP + px] =
                pk2(xb[(size_t)(2 * k2) * Np + px], xb[(size_t)(2 * k2 + 1) * Np + px]);
        }
    }

    // GEMM tile: 8 oc rows x 4 px per thread (px = 2*pg+{0,1} + 32*jj)
    const int ocg = tid >> 4;          // 0..15
    const int r0  = ocg * 8;
    const int pg  = tid & 15;
    const bool isK = (r0 < 64);

    // stage-B identity: 64 pm x 4 slices of 16 px
    const int pm = tid & 63, slice = tid >> 6, p8 = pm & 56;
    float racc[8] = {0, 0, 0, 0, 0, 0, 0, 0};
    float rks = 0.0f;
    int bprev = t0 / TPBATCH;

#define P1_FLUSH(BIDX)                                                        \
    do {                                                                      \
        __syncthreads();                                                      \
        _Pragma("unroll")                                                     \
        for (int c = 0; c < 8; c++) sRed[tid * 9 + c] = racc[c];              \
        sRed[tid * 9 + 8] = rks;                                              \
        __syncthreads();                                                      \
        if (tid < 64) {                                                       \
            float s[9] = {0, 0, 0, 0, 0, 0, 0, 0, 0};                         \
            _Pragma("unroll")                                                 \
            for (int sl = 0; sl < 4; sl++) {                                  \
                const float* p = sRed + (sl * 64 + tid) * 9;                  \
                _Pragma("unroll")                                             \
                for (int c = 0; c < 9; c++) s[c] += p[c];                     \
            }                                                                 \
            _Pragma("unroll")                                                 \
            for (int c = 0; c < 8; c++)                                       \
                atomicAdd(g_attn + ((BIDX) * 64 + tid) * 8 + c, s[c]);        \
            atomicAdd(g_ksum_raw + (BIDX) * 64 + tid, s[8]);                  \
        }                                                                     \
        _Pragma("unroll")                                                     \
        for (int c = 0; c < 8; c++) racc[c] = 0.0f;                           \
        rks = 0.0f;                                                           \
    } while (0)

    for (int t = t0; t < t1; ++t) {
        const int b = t / TPBATCH;
        if (b != bprev) { P1_FLUSH(bprev); bprev = b; }

        __syncthreads();   // staged buf visible; sKV free (prev stage-B done)
        u64* sXc = (t & 1) ? sX1 : sX0;
        u64* sXn = (t & 1) ? sX0 : sX1;

        // ---- GEMM: 128 rows x 64 px over 32 k2 ----
        u64 acc[32];
#pragma unroll
        for (int i = 0; i < 32; i++) acc[i] = 0ull;
#pragma unroll 4
        for (int k2 = 0; k2 < 32; k2++) {
            const ulonglong2* wp = (const ulonglong2*)(sW + k2 * 128 + r0);
            ulonglong2 w01 = wp[0], w23 = wp[1], w45 = wp[2], w67 = wp[3];
            u64 w2r[8] = {w01.x, w01.y, w23.x, w23.y, w45.x, w45.y, w67.x, w67.y};
            ulonglong2 xa = *(const ulonglong2*)(sXc + k2 * XP + 2 * pg);
            ulonglong2 xc = *(const ulonglong2*)(sXc + k2 * XP + 32 + 2 * pg);
            u64 x2r[4] = {xa.x, xa.y, xc.x, xc.y};
#pragma unroll
            for (int oi = 0; oi < 8; oi++)
#pragma unroll
                for (int j = 0; j < 4; j++)
                    acc[oi * 4 + j] = ffma2(w2r[oi], x2r[j], acc[oi * 4 + j]);
        }

        // ---- prefetch next tile's inputs into regs (LDG hidden by epilogue)
        const bool pfv = (t + 1 < t1);
        u64 pf[8];
        if (pfv) {
            const int t2 = t + 1;
            const int b2 = t2 / TPBATCH;
            const int n2 = (t2 % TPBATCH) * TILE;
            const float* xb2 = low + ((size_t)b2 * 64) * Np + n2;
#pragma unroll
            for (int it = 0; it < 8; it++) {
                int idx = tid + TPB * it;
                int k2 = idx >> 6, px = idx & 63;
                pf[it] = pk2(xb2[(size_t)(2 * k2) * Np + px],
                             xb2[(size_t)(2 * k2 + 1) * Np + px]);
            }
        }

        // ---- epilogue -> sKV (paired STS.64) ----
#pragma unroll
        for (int oi = 0; oi < 8; oi++) {
            const int r = r0 + oi;
            const float bias = sb[r];
#pragma unroll
            for (int jj = 0; jj < 2; jj++) {
                float lo0, hi0, lo1, hi1;
                upk2(acc[oi * 4 + 2 * jj], lo0, hi0);
                upk2(acc[oi * 4 + 2 * jj + 1], lo1, hi1);
                float v0 = lo0 + hi0 + bias;
                float v1 = lo1 + hi1 + bias;
                if (isK) { v0 = softplus(v0); v1 = softplus(v1); }
                *(u64*)(sKV + r * KP + 2 * pg + 32 * jj) = pk2(v0, v1);
            }
        }

        // ---- store prefetched tile into the other buffer ----
        if (pfv) {
#pragma unroll
            for (int it = 0; it < 8; it++) {
                int idx = tid + TPB * it;
                int k2 = idx >> 6, px = idx & 63;
                sXn[k2 * XP + px] = pf[it];
            }
        }
        __syncthreads();   // sKV visible; STS(next tile) drained

        // ---- stage B: attn reduce (float4 reads) ----
        const float* kr = sKV + pm * KP + slice * 16;
        const float* vr = sKV + (64 + p8) * KP + slice * 16;
#pragma unroll
        for (int ii = 0; ii < 4; ii++) {
            float4 kq = *(const float4*)(kr + 4 * ii);
            rks += (kq.x + kq.y) + (kq.z + kq.w);
#pragma unroll
            for (int c = 0; c < 8; c++) {
                float4 vq = *(const float4*)(vr + c * KP + 4 * ii);
                racc[c] += kq.x * vq.x + kq.y * vq.y + kq.z * vq.z + kq.w * vq.w;
            }
        }
    }
    P1_FLUSH(bprev);
#undef P1_FLUSH
}

// ---------------------------------------------------------------------------
__global__ __launch_bounds__(512, 1)
void prep(const float* __restrict__ wo) {
    __shared__ float sA[512];
    const int tid = threadIdx.x;
    const int b = blockIdx.x;
    sA[tid] = g_attn[b * 512 + tid];
    if (tid < 64) g_ksum[b * 64 + tid] = g_ksum_raw[b * 64 + tid] + EPSV;
    __syncthreads();
    for (int idx = tid; idx < 4096; idx += 512) {
        int o = idx >> 6, pm = idx & 63;
        const float* wr = wo + o * 64 + (pm & 56);
        const float* ar = sA + pm * 8;
        float acc = 0.0f;
#pragma unroll
        for (int c = 0; c < 8; c++) acc += wr[c] * ar[c];
        g_W2[b * 4096 + ((pm >> 1) * 64 + o) * 2 + (pm & 1)] = acc;
    }
}

// ---------------------------------------------------------------------------
// pass2 (R9, known-good): ~84KB smem, 2 blocks/SM.
// GEMM phases use threads 0..127 at 8 rows x 4 px (wf/FMA2 = 0.375).
// ---------------------------------------------------------------------------
__global__ __launch_bounds__(TPB, 2)
void pass2(const float* __restrict__ high, const float* __restrict__ low,
           const float* __restrict__ wqh, const float* __restrict__ bqh,
           const float* __restrict__ wql, const float* __restrict__ bql,
           const float* __restrict__ bo, float* __restrict__ out) {
    extern __shared__ u64 smu[];
    u64*   sWq  = smu;                         // 2048
    u64*   sW2  = smu + 2048;                  // 2048
    u64*   sXh  = smu + 4096;                  // 2112
    u64*   sXl  = smu + 4096 + 2112;           // 2112
    u64*   sQ   = smu + 4096 + 2 * 2112;       // 2112
    u64*   sks2 = smu + 4096 + 3 * 2112;       // 32
    float* sbq  = (float*)(sks2 + 32);         // 64
    float* sbo  = sbq + 64;                    // 64

    const int tid = threadIdx.x;
    const int blk = blockIdx.x;
    const int t0 = (int)(((long long)blk * TILES_TOTAL) / GRID);
    const int t1 = (int)(((long long)(blk + 1) * TILES_TOTAL) / GRID);

    for (int i = tid; i < 2048; i += TPB) {
        int k2 = i >> 6, r = i & 63;
        const float* Wr = (r < 32) ? (wqh + r * 64) : (wql + (r - 32) * 64);
        sWq[k2 * 64 + r] = pk2(Wr[2 * k2], Wr[2 * k2 + 1]);
    }
    if (tid < 32) sbq[tid] = bqh[tid];
    else if (tid < 64) sbq[tid] = bql[tid - 32];
    else if (tid < 128) sbo[tid - 64] = bo[tid - 64];

    // GEMM coords (threads 0..127 active): 8 rows x 4 px
    const int ocg = (tid & 127) >> 4;        // 0..7
    const int rG  = ocg * 8;                 // rows rG..rG+7 (GEMM1: 0..31 high, 32..63 low)
    const int pg  = tid & 15;                // px = 2*pg + {0,1} + 32*jj
    const bool gActive = (tid < 128);

    int bprev = -1;

    for (int t = t0; t < t1; ++t) {
        const int b = t / TPBATCH;
        if (b != bprev) {
            __syncthreads();   // prior GEMM2/norm readers of sW2/sks2 done
            const u64* gW2 = (const u64*)g_W2 + (size_t)b * 2048;
            for (int i = tid; i < 2048; i += TPB) sW2[i] = gW2[i];
            if (tid < 32)
                sks2[tid] = pk2(g_ksum[b * 64 + 2 * tid], g_ksum[b * 64 + 2 * tid + 1]);
            bprev = b;
        }
        const int n0 = (t % TPBATCH) * TILE;
        const float* xh = high + ((size_t)b * 64) * Np + n0;
        const float* xl = low  + ((size_t)b * 64) * Np + n0;

        __syncthreads();
#pragma unroll
        for (int it = 0; it < 8; it++) {
            int idx = tid + TPB * it;          // 0..2047
            int k2 = idx >> 6, px = idx & 63;
            sXh[k2 * XP + px] =
                pk2(xh[(size_t)(2 * k2) * Np + px], xh[(size_t)(2 * k2 + 1) * Np + px]);
            sXl[k2 * XP + px] =
                pk2(xl[(size_t)(2 * k2) * Np + px], xl[(size_t)(2 * k2 + 1) * Np + px]);
        }
        __syncthreads();

        // ---- GEMM1: q = softplus(Wq @ X) -> sQ packed (threads 0..127) ----
        if (gActive) {
            const u64* sXin = (rG < 32) ? sXh : sXl;
            u64 acc[32];
#pragma unroll
            for (int i = 0; i < 32; i++) acc[i] = 0ull;
#pragma unroll 4
            for (int k2 = 0; k2 < 32; k2++) {
                const ulonglong2* wp = (const ulonglong2*)(sWq + k2 * 64 + rG);
                ulonglong2 w01 = wp[0], w23 = wp[1], w45 = wp[2], w67 = wp[3];
                u64 w2r[8] = {w01.x, w01.y, w23.x, w23.y, w45.x, w45.y, w67.x, w67.y};
                ulonglong2 xa = *(const ulonglong2*)(sXin + k2 * XP + 2 * pg);
                ulonglong2 xc = *(const ulonglong2*)(sXin + k2 * XP + 32 + 2 * pg);
                u64 x2r[4] = {xa.x, xa.y, xc.x, xc.y};
#pragma unroll
                for (int oi = 0; oi < 8; oi++)
#pragma unroll
                    for (int j = 0; j < 4; j++)
                        acc[oi * 4 + j] = ffma2(w2r[oi], x2r[j], acc[oi * 4 + j]);
            }
            // epilogue: bias + softplus, pack row-pairs into sQ
#pragma unroll
            for (int oi2 = 0; oi2 < 4; oi2++) {
                const int ra = rG + 2 * oi2;
                const float ba0 = sbq[ra], ba1 = sbq[ra + 1];
#pragma unroll
                for (int jj = 0; jj < 2; jj++) {
                    float lo, hi;
                    upk2(acc[(2 * oi2) * 4 + 2 * jj], lo, hi);
                    float v00 = softplus(lo + hi + ba0);
                    upk2(acc[(2 * oi2) * 4 + 2 * jj + 1], lo, hi);
                    float v01 = softplus(lo + hi + ba0);
                    upk2(acc[(2 * oi2 + 1) * 4 + 2 * jj], lo, hi);
                    float v10 = softplus(lo + hi + ba1);
                    upk2(acc[(2 * oi2 + 1) * 4 + 2 * jj + 1], lo, hi);
                    float v11 = softplus(lo + hi + ba1);
                    ulonglong2 st;
                    st.x = pk2(v00, v10);
                    st.y = pk2(v01, v11);
                    *(ulonglong2*)(sQ + (ra >> 1) * XP + 32 * jj + 2 * pg) = st;
                }
            }
        }
        __syncthreads();

        // ---- fused norm + in-place rescale (all 256 threads) ----
#pragma unroll
        for (int rr = 0; rr < 2; rr++) {
            int it = tid + TPB * rr;           // 0..511
            int h = it >> 6, px = it & 63;
            u64 q0 = sQ[(h * 4 + 0) * XP + px];
            u64 q1 = sQ[(h * 4 + 1) * XP + px];
            u64 q2 = sQ[(h * 4 + 2) * XP + px];
            u64 q3 = sQ[(h * 4 + 3) * XP + px];
            u64 a = ffma2(q0, sks2[h * 4 + 0], 0ull);
            a = ffma2(q1, sks2[h * 4 + 1], a);
            a = ffma2(q2, sks2[h * 4 + 2], a);
            a = ffma2(q3, sks2[h * 4 + 3], a);
            float lo, hi; upk2(a, lo, hi);
            float inv = 1.0f / (lo + hi);
            u64 iv = pk2(inv, inv);
            sQ[(h * 4 + 0) * XP + px] = fmul2(q0, iv);
            sQ[(h * 4 + 1) * XP + px] = fmul2(q1, iv);
            sQ[(h * 4 + 2) * XP + px] = fmul2(q2, iv);
            sQ[(h * 4 + 3) * XP + px] = fmul2(q3, iv);
        }
        __syncthreads();

        // ---- GEMM2: out = W2 @ q' + bo (threads 0..127) ----
        if (gActive) {
            u64 acc[32];
#pragma unroll
            for (int i = 0; i < 32; i++) acc[i] = 0ull;
#pragma unroll 4
            for (int k2 = 0; k2 < 32; k2++) {
                const ulonglong2* wp = (const ulonglong2*)(sW2 + k2 * 64 + rG);
                ulonglong2 w01 = wp[0], w23 = wp[1], w45 = wp[2], w67 = wp[3];
                u64 w2r[8] = {w01.x, w01.y, w23.x, w23.y, w45.x, w45.y, w67.x, w67.y};
                ulonglong2 xa = *(const ulonglong2*)(sQ + k2 * XP + 2 * pg);
                ulonglong2 xc = *(const ulonglong2*)(sQ + k2 * XP + 32 + 2 * pg);
                u64 x2r[4] = {xa.x, xa.y, xc.x, xc.y};
#pragma unroll
                for (int oi = 0; oi < 8; oi++)
#pragma unroll
                    for (int j = 0; j < 4; j++)
                        acc[oi * 4 + j] = ffma2(w2r[oi], x2r[j], acc[oi * 4 + j]);
            }
            float* ob = out + ((size_t)b * 64) * Np + n0;
#pragma unroll
            for (int oi = 0; oi < 8; oi++) {
                const int r = rG + oi;
                const float bias = sbo[r];
#pragma unroll
                for (int jj = 0; jj < 2; jj++) {
                    float lo0, hi0, lo1, hi1;
                    upk2(acc[oi * 4 + 2 * jj], lo0, hi0);
                    upk2(acc[oi * 4 + 2 * jj + 1], lo1, hi1);
                    *(float2*)(ob + (size_t)r * Np + 32 * jj + 2 * pg) =
                        make_float2(lo0 + hi0 + bias, lo1 + hi1 + bias);
                }
            }
        }
    }
}

constexpr int SMEM1 = (4096 + 2 * 2112) * 8 + (128 * KP + 128) * 4;   // 101,888
constexpr int SMEM2 = (4096 + 3 * 2112 + 32) * 8 + 128 * 4;           // 84,224

}  // namespace mca

// ---------------------------------------------------------------------------
extern "C" void kernel_launch(void* const* d_in, const int* in_sizes, int n_in,
                              void* d_out, int out_size) {
    using namespace mca;
    (void)in_sizes; (void)n_in; (void)out_size;

    const float* high = (const float*)d_in[0];
    const float* low  = (const float*)d_in[1];
    const float* wqh  = (const float*)d_in[2];
    const float* bqh  = (const float*)d_in[3];
    const float* wql  = (const float*)d_in[4];
    const float* bql  = (const float*)d_in[5];
    const float* wk   = (const float*)d_in[6];
    const float* bk   = (const float*)d_in[7];
    const float* wv   = (const float*)d_in[8];
    const float* bv   = (const float*)d_in[9];
    const float* wo   = (const float*)d_in[10];
    const float* bo   = (const float*)d_in[11];
    float* out = (float*)d_out;

    cudaFuncSetAttribute(pass1, cudaFuncAttributeMaxDynamicSharedMemorySize, SMEM1);
    cudaFuncSetAttribute(pass2, cudaFuncAttributeMaxDynamicSharedMemorySize, SMEM2);

    zero_scratch<<<8, 512>>>();
    pass1<<<GRID, TPB, SMEM1>>>(low, wk, bk, wv, bv);
    prep<<<Bn, 512>>>(wo);
    pass2<<<GRID, TPB, SMEM2>>>(high, low, wqh, bqh, wql, bql, bo, out);
}

// round 14
// speedup vs baseline: 1.7061x; 1.0265x over previous
#include <cuda_runtime.h>

// ---------------------------------------------------------------------------
// MCA linear attention, fp32, FFMA2 register-tiled GEMMs.
// R13: pass2 GEMMs use ALL 256 threads (4 rows x 4 px tiles -> 16 active
//      warps/SM, 2x latency hiding); pass1 stage-B reduce vectorized to f32x2
//      (144 scalar FMA -> 96 FMA2-class per thread).
// ---------------------------------------------------------------------------

#define DINL __device__ __forceinline__
typedef unsigned long long u64;

namespace mca {

constexpr int Bn = 8;
constexpr int Np = 25600;
constexpr int TILE = 64;            // pixels per tile
constexpr int TPB = 256;
constexpr int GRID = 296;           // 2 blocks per SM
constexpr int TILES_TOTAL = 3200;   // Bn*Np/TILE
constexpr int TPBATCH = 400;        // tiles per batch
constexpr int XP = 66;              // u64 pitch for packed activations (64 px)
constexpr int KP = 68;              // f32 pitch for k/v staging (u64 pitch 34)
constexpr float EPSV = 1e-6f;

__device__ float g_attn[Bn * 64 * 8];   // [b][pm][c]  (atomic accum)
__device__ float g_ksum_raw[Bn * 64];
__device__ float g_ksum[Bn * 64];       // +eps
__device__ float g_W2[Bn * 4096];       // dense packed; u64 view: [b*2048 + k2*64 + o]

DINL u64 pk2(float lo, float hi) {
    u64 r; asm("mov.b64 %0, {%1, %2};" : "=l"(r) : "f"(lo), "f"(hi)); return r;
}
DINL void upk2(u64 v, float& lo, float& hi) {
    asm("mov.b64 {%0, %1}, %2;" : "=f"(lo), "=f"(hi) : "l"(v));
}
DINL u64 ffma2(u64 a, u64 b, u64 c) {
    u64 d; asm("fma.rn.f32x2 %0, %1, %2, %3;" : "=l"(d) : "l"(a), "l"(b), "l"(c));
    return d;
}
DINL u64 fadd2(u64 a, u64 b) {
    u64 d; asm("add.rn.f32x2 %0, %1, %2;" : "=l"(d) : "l"(a), "l"(b));
    return d;
}
DINL u64 fmul2(u64 a, u64 b) {
    u64 d; asm("mul.rn.f32x2 %0, %1, %2;" : "=l"(d) : "l"(a), "l"(b));
    return d;
}
// Fast stable softplus: arg of __logf is in (1,2], no overflow anywhere.
DINL float softplus(float x) {
    float e = __expf(-fabsf(x));
    return fmaxf(x, 0.0f) + __logf(1.0f + e);
}

// ---------------------------------------------------------------------------
__global__ void zero_scratch() {
    int i = blockIdx.x * blockDim.x + threadIdx.x;
    int stride = gridDim.x * blockDim.x;
    for (int j = i; j < Bn * 64 * 8; j += stride) g_attn[j] = 0.0f;
    for (int j = i; j < Bn * 64; j += stride) g_ksum_raw[j] = 0.0f;
}

// ---------------------------------------------------------------------------
// pass1 smem (u64-first):
//   sW [4096] u64, sX0 [2112] u64, sX1 [2112] u64 (double buffer),
//   sKV [128*68] f32 (aliased by sRed during flush), sb [128]
//   total 101,888 B -> 2 blocks/SM
// ---------------------------------------------------------------------------
__global__ __launch_bounds__(TPB, 2)
void pass1(const float* __restrict__ low,
           const float* __restrict__ wk, const float* __restrict__ bk,
           const float* __restrict__ wv, const float* __restrict__ bv) {
    extern __shared__ u64 smu[];
    u64*   sW  = smu;                          // 4096
    u64*   sX0 = smu + 4096;                   // 2112
    u64*   sX1 = smu + 4096 + 2112;            // 2112
    float* sKV = (float*)(smu + 4096 + 4224);  // 128*KP
    float* sb  = sKV + 128 * KP;               // 128
    float* sRed = sKV;                         // alias (flush only; sKV dead then)

    const int tid = threadIdx.x;
    const int blk = blockIdx.x;
    const int t0 = (int)(((long long)blk * TILES_TOTAL) / GRID);
    const int t1 = (int)(((long long)(blk + 1) * TILES_TOTAL) / GRID);

    for (int i = tid; i < 4096; i += TPB) {
        int k2 = i >> 7, r = i & 127;
        const float* Wr = (r < 64) ? (wk + r * 64) : (wv + (r - 64) * 64);
        sW[k2 * 128 + r] = pk2(Wr[2 * k2], Wr[2 * k2 + 1]);
    }
    if (tid < 64) sb[tid] = bk[tid];
    else if (tid < 128) sb[tid] = bv[tid - 64];

    // prologue: stage tile t0 into buf[t0&1]
    {
        const int bb = t0 / TPBATCH;
        const int n00 = (t0 % TPBATCH) * TILE;
        const float* xb = low + ((size_t)bb * 64) * Np + n00;
        u64* sXc = (t0 & 1) ? sX1 : sX0;
#pragma unroll
        for (int it = 0; it < 8; it++) {
            int idx = tid + TPB * it;
            int k2 = idx >> 6, px = idx & 63;
            sXc[k2 * XP + px] =
                pk2(xb[(size_t)(2 * k2) * Np + px], xb[(size_t)(2 * k2 + 1) * Np + px]);
        }
    }

    // GEMM tile: 8 oc rows x 4 px per thread (px = 2*pg+{0,1} + 32*jj)
    const int ocg = tid >> 4;          // 0..15
    const int r0  = ocg * 8;
    const int pg  = tid & 15;
    const bool isK = (r0 < 64);

    // stage-B identity: 64 pm x 4 slices of 16 px (f32x2 over px)
    const int pm = tid & 63, slice = tid >> 6, p8 = pm & 56;
    u64 racc2[8] = {0, 0, 0, 0, 0, 0, 0, 0};
    u64 rks2 = 0ull;
    int bprev = t0 / TPBATCH;

#define P1_FLUSH(BIDX)                                                        \
    do {                                                                      \
        __syncthreads();                                                      \
        _Pragma("unroll")                                                     \
        for (int c = 0; c < 8; c++) {                                         \
            float lo, hi; upk2(racc2[c], lo, hi);                             \
            sRed[tid * 9 + c] = lo + hi;                                      \
        }                                                                     \
        { float lo, hi; upk2(rks2, lo, hi); sRed[tid * 9 + 8] = lo + hi; }    \
        __syncthreads();                                                      \
        if (tid < 64) {                                                       \
            float s[9] = {0, 0, 0, 0, 0, 0, 0, 0, 0};                         \
            _Pragma("unroll")                                                 \
            for (int sl = 0; sl < 4; sl++) {                                  \
                const float* p = sRed + (sl * 64 + tid) * 9;                  \
                _Pragma("unroll")                                             \
                for (int c = 0; c < 9; c++) s[c] += p[c];                     \
            }                                                                 \
            _Pragma("unroll")                                                 \
            for (int c = 0; c < 8; c++)                                       \
                atomicAdd(g_attn + ((BIDX) * 64 + tid) * 8 + c, s[c]);        \
            atomicAdd(g_ksum_raw + (BIDX) * 64 + tid, s[8]);                  \
        }                                                                     \
        _Pragma("unroll")                                                     \
        for (int c = 0; c < 8; c++) racc2[c] = 0ull;                          \
        rks2 = 0ull;                                                          \
    } while (0)

    for (int t = t0; t < t1; ++t) {
        const int b = t / TPBATCH;
        if (b != bprev) { P1_FLUSH(bprev); bprev = b; }

        __syncthreads();   // staged buf visible; sKV free (prev stage-B done)
        u64* sXc = (t & 1) ? sX1 : sX0;
        u64* sXn = (t & 1) ? sX0 : sX1;

        // ---- GEMM: 128 rows x 64 px over 32 k2 ----
        u64 acc[32];
#pragma unroll
        for (int i = 0; i < 32; i++) acc[i] = 0ull;
#pragma unroll 4
        for (int k2 = 0; k2 < 32; k2++) {
            const ulonglong2* wp = (const ulonglong2*)(sW + k2 * 128 + r0);
            ulonglong2 w01 = wp[0], w23 = wp[1], w45 = wp[2], w67 = wp[3];
            u64 w2r[8] = {w01.x, w01.y, w23.x, w23.y, w45.x, w45.y, w67.x, w67.y};
            ulonglong2 xa = *(const ulonglong2*)(sXc + k2 * XP + 2 * pg);
            ulonglong2 xc = *(const ulonglong2*)(sXc + k2 * XP + 32 + 2 * pg);
            u64 x2r[4] = {xa.x, xa.y, xc.x, xc.y};
#pragma unroll
            for (int oi = 0; oi < 8; oi++)
#pragma unroll
                for (int j = 0; j < 4; j++)
                    acc[oi * 4 + j] = ffma2(w2r[oi], x2r[j], acc[oi * 4 + j]);
        }

        // ---- prefetch next tile's inputs into regs (LDG hidden by epilogue)
        const bool pfv = (t + 1 < t1);
        u64 pf[8];
        if (pfv) {
            const int t2 = t + 1;
            const int b2 = t2 / TPBATCH;
            const int n2 = (t2 % TPBATCH) * TILE;
            const float* xb2 = low + ((size_t)b2 * 64) * Np + n2;
#pragma unroll
            for (int it = 0; it < 8; it++) {
                int idx = tid + TPB * it;
                int k2 = idx >> 6, px = idx & 63;
                pf[it] = pk2(xb2[(size_t)(2 * k2) * Np + px],
                             xb2[(size_t)(2 * k2 + 1) * Np + px]);
            }
        }

        // ---- epilogue -> sKV (paired STS.64) ----
#pragma unroll
        for (int oi = 0; oi < 8; oi++) {
            const int r = r0 + oi;
            const float bias = sb[r];
#pragma unroll
            for (int jj = 0; jj < 2; jj++) {
                float lo0, hi0, lo1, hi1;
                upk2(acc[oi * 4 + 2 * jj], lo0, hi0);
                upk2(acc[oi * 4 + 2 * jj + 1], lo1, hi1);
                float v0 = lo0 + hi0 + bias;
                float v1 = lo1 + hi1 + bias;
                if (isK) { v0 = softplus(v0); v1 = softplus(v1); }
                *(u64*)(sKV + r * KP + 2 * pg + 32 * jj) = pk2(v0, v1);
            }
        }

        // ---- store prefetched tile into the other buffer ----
        if (pfv) {
#pragma unroll
            for (int it = 0; it < 8; it++) {
                int idx = tid + TPB * it;
                int k2 = idx >> 6, px = idx & 63;
                sXn[k2 * XP + px] = pf[it];
            }
        }
        __syncthreads();   // sKV visible; STS(next tile) drained

        // ---- stage B: attn reduce, f32x2 over pixel pairs ----
        const u64* kr = (const u64*)sKV + pm * 34 + slice * 8;
        const u64* vr = (const u64*)sKV + (64 + p8) * 34 + slice * 8;
#pragma unroll
        for (int ii = 0; ii < 4; ii++) {
            ulonglong2 kq = *(const ulonglong2*)(kr + 2 * ii);
            rks2 = fadd2(rks2, kq.x);
            rks2 = fadd2(rks2, kq.y);
#pragma unroll
            for (int c = 0; c < 8; c++) {
                ulonglong2 vq = *(const ulonglong2*)(vr + c * 34 + 2 * ii);
                racc2[c] = ffma2(kq.x, vq.x, racc2[c]);
                racc2[c] = ffma2(kq.y, vq.y, racc2[c]);
            }
        }
    }
    P1_FLUSH(bprev);
#undef P1_FLUSH
}

// ---------------------------------------------------------------------------
__global__ __launch_bounds__(512, 1)
void prep(const float* __restrict__ wo) {
    __shared__ float sA[512];
    const int tid = threadIdx.x;
    const int b = blockIdx.x;
    sA[tid] = g_attn[b * 512 + tid];
    if (tid < 64) g_ksum[b * 64 + tid] = g_ksum_raw[b * 64 + tid] + EPSV;
    __syncthreads();
    for (int idx = tid; idx < 4096; idx += 512) {
        int o = idx >> 6, pm = idx & 63;
        const float* wr = wo + o * 64 + (pm & 56);
        const float* ar = sA + pm * 8;
        float acc = 0.0f;
#pragma unroll
        for (int c = 0; c < 8; c++) acc += wr[c] * ar[c];
        g_W2[b * 4096 + ((pm >> 1) * 64 + o) * 2 + (pm & 1)] = acc;
    }
}

// ---------------------------------------------------------------------------
// pass2: ~84KB smem, 2 blocks/SM. GEMMs use ALL 256 threads at 4 rows x 4 px
// (16 active warps/SM during GEMM phases).
// ---------------------------------------------------------------------------
__global__ __launch_bounds__(TPB, 2)
void pass2(const float* __restrict__ high, const float* __restrict__ low,
           const float* __restrict__ wqh, const float* __restrict__ bqh,
           const float* __restrict__ wql, const float* __restrict__ bql,
           const float* __restrict__ bo, float* __restrict__ out) {
    extern __shared__ u64 smu[];
    u64*   sWq  = smu;                         // 2048
    u64*   sW2  = smu + 2048;                  // 2048
    u64*   sXh  = smu + 4096;                  // 2112
    u64*   sXl  = smu + 4096 + 2112;           // 2112
    u64*   sQ   = smu + 4096 + 2 * 2112;       // 2112
    u64*   sks2 = smu + 4096 + 3 * 2112;       // 32
    float* sbq  = (float*)(sks2 + 32);         // 64
    float* sbo  = sbq + 64;                    // 64

    const int tid = threadIdx.x;
    const int blk = blockIdx.x;
    const int t0 = (int)(((long long)blk * TILES_TOTAL) / GRID);
    const int t1 = (int)(((long long)(blk + 1) * TILES_TOTAL) / GRID);

    for (int i = tid; i < 2048; i += TPB) {
        int k2 = i >> 6, r = i & 63;
        const float* Wr = (r < 32) ? (wqh + r * 64) : (wql + (r - 32) * 64);
        sWq[k2 * 64 + r] = pk2(Wr[2 * k2], Wr[2 * k2 + 1]);
    }
    if (tid < 32) sbq[tid] = bqh[tid];
    else if (tid < 64) sbq[tid] = bql[tid - 32];
    else if (tid < 128) sbo[tid - 64] = bo[tid - 64];

    // GEMM coords (all 256 threads): 4 rows x 4 px
    const int rG = (tid >> 4) * 4;           // 0,4,...,60
    const int pg = tid & 15;                 // px = 2*pg + {0,1} + 32*jj

    int bprev = -1;

    for (int t = t0; t < t1; ++t) {
        const int b = t / TPBATCH;
        if (b != bprev) {
            __syncthreads();   // prior GEMM2/norm readers of sW2/sks2 done
            const u64* gW2 = (const u64*)g_W2 + (size_t)b * 2048;
            for (int i = tid; i < 2048; i += TPB) sW2[i] = gW2[i];
            if (tid < 32)
                sks2[tid] = pk2(g_ksum[b * 64 + 2 * tid], g_ksum[b * 64 + 2 * tid + 1]);
            bprev = b;
        }
        const int n0 = (t % TPBATCH) * TILE;
        const float* xh = high + ((size_t)b * 64) * Np + n0;
        const float* xl = low  + ((size_t)b * 64) * Np + n0;

        __syncthreads();
#pragma unroll
        for (int it = 0; it < 8; it++) {
            int idx = tid + TPB * it;          // 0..2047
            int k2 = idx >> 6, px = idx & 63;
            sXh[k2 * XP + px] =
                pk2(xh[(size_t)(2 * k2) * Np + px], xh[(size_t)(2 * k2 + 1) * Np + px]);
            sXl[k2 * XP + px] =
                pk2(xl[(size_t)(2 * k2) * Np + px], xl[(size_t)(2 * k2 + 1) * Np + px]);
        }
        __syncthreads();

        // ---- GEMM1: q = softplus(Wq @ X) -> sQ packed (all threads) ----
        {
            const u64* sXin = (rG < 32) ? sXh : sXl;
            u64 acc[16];
#pragma unroll
            for (int i = 0; i < 16; i++) acc[i] = 0ull;
#pragma unroll 4
            for (int k2 = 0; k2 < 32; k2++) {
                const ulonglong2* wp = (const ulonglong2*)(sWq + k2 * 64 + rG);
                ulonglong2 w01 = wp[0], w23 = wp[1];
                u64 w2r[4] = {w01.x, w01.y, w23.x, w23.y};
                ulonglong2 xa = *(const ulonglong2*)(sXin + k2 * XP + 2 * pg);
                ulonglong2 xc = *(const ulonglong2*)(sXin + k2 * XP + 32 + 2 * pg);
                u64 x2r[4] = {xa.x, xa.y, xc.x, xc.y};
#pragma unroll
                for (int oi = 0; oi < 4; oi++)
#pragma unroll
                    for (int j = 0; j < 4; j++)
                        acc[oi * 4 + j] = ffma2(w2r[oi], x2r[j], acc[oi * 4 + j]);
            }
            // epilogue: bias + softplus, pack row-pairs into sQ
#pragma unroll
            for (int oi2 = 0; oi2 < 2; oi2++) {
                const int ra = rG + 2 * oi2;
                const float ba0 = sbq[ra], ba1 = sbq[ra + 1];
#pragma unroll
                for (int jj = 0; jj < 2; jj++) {
                    float lo, hi;
                    upk2(acc[(2 * oi2) * 4 + 2 * jj], lo, hi);
                    float v00 = softplus(lo + hi + ba0);
                    upk2(acc[(2 * oi2) * 4 + 2 * jj + 1], lo, hi);
                    float v01 = softplus(lo + hi + ba0);
                    upk2(acc[(2 * oi2 + 1) * 4 + 2 * jj], lo, hi);
                    float v10 = softplus(lo + hi + ba1);
                    upk2(acc[(2 * oi2 + 1) * 4 + 2 * jj + 1], lo, hi);
                    float v11 = softplus(lo + hi + ba1);
                    ulonglong2 st;
                    st.x = pk2(v00, v10);
                    st.y = pk2(v01, v11);
                    *(ulonglong2*)(sQ + (ra >> 1) * XP + 32 * jj + 2 * pg) = st;
                }
            }
        }
        __syncthreads();

        // ---- fused norm + in-place rescale (all 256 threads) ----
#pragma unroll
        for (int rr = 0; rr < 2; rr++) {
            int it = tid + TPB * rr;           // 0..511
            int h = it >> 6, px = it & 63;
            u64 q0 = sQ[(h * 4 + 0) * XP + px];
            u64 q1 = sQ[(h * 4 + 1) * XP + px];
            u64 q2 = sQ[(h * 4 + 2) * XP + px];
            u64 q3 = sQ[(h * 4 + 3) * XP + px];
            u64 a = ffma2(q0, sks2[h * 4 + 0], 0ull);
            a = ffma2(q1, sks2[h * 4 + 1], a);
            a = ffma2(q2, sks2[h * 4 + 2], a);
            a = ffma2(q3, sks2[h * 4 + 3], a);
            float lo, hi; upk2(a, lo, hi);
            float inv = 1.0f / (lo + hi);
            u64 iv = pk2(inv, inv);
            sQ[(h * 4 + 0) * XP + px] = fmul2(q0, iv);
            sQ[(h * 4 + 1) * XP + px] = fmul2(q1, iv);
            sQ[(h * 4 + 2) * XP + px] = fmul2(q2, iv);
            sQ[(h * 4 + 3) * XP + px] = fmul2(q3, iv);
        }
        __syncthreads();

        // ---- GEMM2: out = W2 @ q' + bo (all threads) ----
        {
            u64 acc[16];
#pragma unroll
            for (int i = 0; i < 16; i++) acc[i] = 0ull;
#pragma unroll 4
            for (int k2 = 0; k2 < 32; k2++) {
                const ulonglong2* wp = (const ulonglong2*)(sW2 + k2 * 64 + rG);
                ulonglong2 w01 = wp[0], w23 = wp[1];
                u64 w2r[4] = {w01.x, w01.y, w23.x, w23.y};
                ulonglong2 xa = *(const ulonglong2*)(sQ + k2 * XP + 2 * pg);
                ulonglong2 xc = *(const ulonglong2*)(sQ + k2 * XP + 32 + 2 * pg);
                u64 x2r[4] = {xa.x, xa.y, xc.x, xc.y};
#pragma unroll
                for (int oi = 0; oi < 4; oi++)
#pragma unroll
                    for (int j = 0; j < 4; j++)
                        acc[oi * 4 + j] = ffma2(w2r[oi], x2r[j], acc[oi * 4 + j]);
            }
            float* ob = out + ((size_t)b * 64) * Np + n0;
#pragma unroll
            for (int oi = 0; oi < 4; oi++) {
                const int r = rG + oi;
                const float bias = sbo[r];
#pragma unroll
                for (int jj = 0; jj < 2; jj++) {
                    float lo0, hi0, lo1, hi1;
                    upk2(acc[oi * 4 + 2 * jj], lo0, hi0);
                    upk2(acc[oi * 4 + 2 * jj + 1], lo1, hi1);
                    *(float2*)(ob + (size_t)r * Np + 32 * jj + 2 * pg) =
                        make_float2(lo0 + hi0 + bias, lo1 + hi1 + bias);
                }
            }
        }
    }
}

constexpr int SMEM1 = (4096 + 2 * 2112) * 8 + (128 * KP + 128) * 4;   // 101,888
constexpr int SMEM2 = (4096 + 3 * 2112 + 32) * 8 + 128 * 4;           // 84,224

}  // namespace mca

// ---------------------------------------------------------------------------
extern "C" void kernel_launch(void* const* d_in, const int* in_sizes, int n_in,
                              void* d_out, int out_size) {
    using namespace mca;
    (void)in_sizes; (void)n_in; (void)out_size;

    const float* high = (const float*)d_in[0];
    const float* low  = (const float*)d_in[1];
    const float* wqh  = (const float*)d_in[2];
    const float* bqh  = (const float*)d_in[3];
    const float* wql  = (const float*)d_in[4];
    const float* bql  = (const float*)d_in[5];
    const float* wk   = (const float*)d_in[6];
    const float* bk   = (const float*)d_in[7];
    const float* wv   = (const float*)d_in[8];
    const float* bv   = (const float*)d_in[9];
    const float* wo   = (const float*)d_in[10];
    const float* bo   = (const float*)d_in[11];
    float* out = (float*)d_out;

    cudaFuncSetAttribute(pass1, cudaFuncAttributeMaxDynamicSharedMemorySize, SMEM1);
    cudaFuncSetAttribute(pass2, cudaFuncAttributeMaxDynamicSharedMemorySize, SMEM2);

    zero_scratch<<<8, 512>>>();
    pass1<<<GRID, TPB, SMEM1>>>(low, wk, bk, wv, bv);
    prep<<<Bn, 512>>>(wo);
    pass2<<<GRID, TPB, SMEM2>>>(high, low, wqh, bqh, wql, bql, bo, out);
}